// round 2
// baseline (speedup 1.0000x reference)
#include <cuda_runtime.h>

#define RR 16384
#define SS 64
#define GG 128
#define EE 16
#define NPTS (RR*SS)
#define SX (GG*GG*EE)
#define SY (GG*EE)

// ---- scratch (per-point) ----
__device__ float4 g_srgb[NPTS];   // (sigma, r, g, b)
__device__ float4 g_nrm[NPTS];    // (nx, ny, nz, 0)

// near/far arrive as 1-element scalars; dtype (int32/int64/float32) unknown -> decode robustly.
__device__ __forceinline__ float decode_scalar(const unsigned* p){
  unsigned u = *p;
  if (u == 0u) return 0.0f;
  if ((u >> 23) == 0u) return (float)(int)u;   // small integer bit pattern
  return __uint_as_float(u);
}
__device__ __forceinline__ float dot4(float4 a, float4 b){
  return fmaf(a.x,b.x, fmaf(a.y,b.y, fmaf(a.z,b.z, a.w*b.w)));
}
__device__ __forceinline__ float4 fma4(float w, float4 v, float4 a){
  a.x=fmaf(w,v.x,a.x); a.y=fmaf(w,v.y,a.y); a.z=fmaf(w,v.z,a.z); a.w=fmaf(w,v.w,a.w); return a;
}
// softplus(100 z)/100, numerically stable
__device__ __forceinline__ float softplus100(float z){
  float y = 100.0f*z;
  float t = __expf(-fabsf(y));
  return (fmaxf(y,0.0f) + __logf(1.0f + t)) * 0.01f;
}
// sigmoid(100 z) recovered from h = softplus(100z)/100:  sigma = 1 - exp(-100 h)
__device__ __forceinline__ float dact_h(float h){ return -expm1f(-100.0f*h); }

// shared-memory layout (floats)
#define OFF_W1   0      // 1024  (64x16)
#define OFF_B1   1024   // 64
#define OFF_W2   1088   // 4096  (64x64 row-major)
#define OFF_W2T  5184   // 4096  (transposed: [k][j])
#define OFF_B2   9280   // 64
#define OFF_W3   9344   // 1024  (16x64)
#define OFF_B3   10368  // 16
#define OFF_CW1  10384  // 1152  (64x18)
#define OFF_CB1  11536  // 64
#define OFF_CW2  11600  // 4096
#define OFF_CB2  15696  // 64
#define OFF_CW3  15760  // 192   (3x64)
#define OFF_CB3  15952  // 3
#define SM_FLOATS 15955

__global__ void __launch_bounds__(128, 2)
k_points(const float* __restrict__ rays_o, const float* __restrict__ rays_d,
         const float* __restrict__ grid,
         const float* __restrict__ sw1, const float* __restrict__ sb1,
         const float* __restrict__ sw2, const float* __restrict__ sb2,
         const float* __restrict__ sw3, const float* __restrict__ sb3,
         const float* __restrict__ cw1, const float* __restrict__ cb1,
         const float* __restrict__ cw2, const float* __restrict__ cb2,
         const float* __restrict__ cw3, const float* __restrict__ cb3,
         const float* __restrict__ beta_p,
         const unsigned* __restrict__ near_p, const unsigned* __restrict__ far_p,
         float* __restrict__ out_grads)
{
  extern __shared__ float sm[];
  const int tid = threadIdx.x;

  // ---- cooperative weight staging ----
  for (int i = tid; i < 1024; i += 128){ sm[OFF_W1+i]=sw1[i]; sm[OFF_W3+i]=sw3[i]; }
  for (int i = tid; i < 4096; i += 128){
    float v = sw2[i];
    sm[OFF_W2+i] = v;
    sm[OFF_W2T + ((i&63)<<6) + (i>>6)] = v;  // [k][j] = w2[j][k]
    sm[OFF_CW2+i] = cw2[i];
  }
  for (int i = tid; i < 1152; i += 128) sm[OFF_CW1+i]=cw1[i];
  for (int i = tid; i < 192;  i += 128) sm[OFF_CW3+i]=cw3[i];
  if (tid < 64){ sm[OFF_B1+tid]=sb1[tid]; sm[OFF_B2+tid]=sb2[tid];
                 sm[OFF_CB1+tid]=cb1[tid]; sm[OFF_CB2+tid]=cb2[tid]; }
  if (tid < 16) sm[OFF_B3+tid]=sb3[tid];
  if (tid < 3)  sm[OFF_CB3+tid]=cb3[tid];
  __syncthreads();

  const int p = blockIdx.x*128 + tid;
  if (p >= NPTS) return;
  const int r = p >> 6;
  const int s = p & 63;

  const float nearf = decode_scalar(near_p);
  const float farf  = decode_scalar(far_p);
  const float span  = farf - nearf;
  const float tm = nearf + span * ((s + 0.5f) * (1.0f/64.0f));

  const float px = fmaf(tm, rays_d[3*r+0], rays_o[3*r+0]);
  const float py = fmaf(tm, rays_d[3*r+1], rays_o[3*r+1]);
  const float pz = fmaf(tm, rays_d[3*r+2], rays_o[3*r+2]);

  // ---- trilinear setup ----
  const float HALF = 0.5f*(float)(GG-1);
  float grx = (px*(1.0f/1.3f) + 1.0f)*HALF;
  float gry = (py*(1.0f/1.3f) + 1.0f)*HALF;
  float grz = (pz*(1.0f/1.3f) + 1.0f)*HALF;
  const float GM1 = (float)(GG-1);
  const bool ax = (grx >= 0.0f) && (grx <= GM1);
  const bool ay = (gry >= 0.0f) && (gry <= GM1);
  const bool az = (grz >= 0.0f) && (grz <= GM1);
  const bool mask = ax && ay && az;
  float gcx = fminf(fmaxf(grx,0.0f), GM1);
  float gcy = fminf(fmaxf(gry,0.0f), GM1);
  float gcz = fminf(fmaxf(grz,0.0f), GM1);
  int ix = min((int)gcx, GG-2);
  int iy = min((int)gcy, GG-2);
  int iz = min((int)gcz, GG-2);
  const float fx = gcx - (float)ix;
  const float fy = gcy - (float)iy;
  const float fz = gcz - (float)iz;
  const int base = ((ix*GG + iy)*GG + iz)*EE;

  // ---- forward gather: emb[16] as 4x float4 ----
  float4 e0={0,0,0,0}, e1=e0, e2=e0, e3=e0;
  #pragma unroll
  for (int dx = 0; dx < 2; ++dx){
    const float wxv = dx ? fx : (1.0f - fx);
    #pragma unroll
    for (int dy = 0; dy < 2; ++dy){
      const float wyv = dy ? fy : (1.0f - fy);
      const float4* gp = (const float4*)(grid + base + dx*SX + dy*SY);
      const float w0 = wxv*wyv*(1.0f - fz);
      const float w1 = wxv*wyv*fz;
      float4 a0=gp[0], a1=gp[1], a2=gp[2], a3=gp[3];
      float4 b0=gp[4], b1=gp[5], b2=gp[6], b3=gp[7];
      e0=fma4(w0,a0,e0); e1=fma4(w0,a1,e1); e2=fma4(w0,a2,e2); e3=fma4(w0,a3,e3);
      e0=fma4(w1,b0,e0); e1=fma4(w1,b1,e1); e2=fma4(w1,b2,e2); e3=fma4(w1,b3,e3);
    }
  }

  // ---- SDF MLP forward ----
  float h1[64];
  #pragma unroll
  for (int j = 0; j < 64; ++j){
    const float4* w = (const float4*)(sm + OFF_W1 + j*16);
    float z = sm[OFF_B1+j] + dot4(w[0],e0) + dot4(w[1],e1) + dot4(w[2],e2) + dot4(w[3],e3);
    h1[j] = softplus100(z);
  }
  float h2[64];
  #pragma unroll
  for (int j = 0; j < 64; ++j){
    const float4* w = (const float4*)(sm + OFF_W2 + j*64);
    float z = sm[OFF_B2+j];
    #pragma unroll
    for (int q = 0; q < 16; ++q){
      float4 ww = w[q];
      z = fmaf(ww.x,h1[4*q+0], fmaf(ww.y,h1[4*q+1], fmaf(ww.z,h1[4*q+2], fmaf(ww.w,h1[4*q+3], z))));
    }
    h2[j] = softplus100(z);
  }
  float sdf;
  float feat[15];
  #pragma unroll
  for (int c = 0; c < 16; ++c){
    const float4* w = (const float4*)(sm + OFF_W3 + c*64);
    float z = sm[OFF_B3+c];
    #pragma unroll
    for (int q = 0; q < 16; ++q){
      float4 ww = w[q];
      z = fmaf(ww.x,h2[4*q+0], fmaf(ww.y,h2[4*q+1], fmaf(ww.z,h2[4*q+2], fmaf(ww.w,h2[4*q+3], z))));
    }
    if (c == 0) sdf = z; else feat[c-1] = z;
  }

  // ---- backward (cotangent e0 on sdf): overwrite h2 with g2 = w3row0 * act'(z2) ----
  #pragma unroll
  for (int j = 0; j < 64; ++j) h2[j] = sm[OFF_W3 + j] * dact_h(h2[j]);

  float4 de0={0,0,0,0}, de1=de0, de2=de0, de3=de0;  // d emb
  #pragma unroll
  for (int k = 0; k < 64; ++k){
    const float4* wt = (const float4*)(sm + OFF_W2T + k*64);  // column k of W2
    float acc = 0.0f;
    #pragma unroll
    for (int q = 0; q < 16; ++q){
      float4 ww = wt[q];
      acc = fmaf(ww.x,h2[4*q+0], fmaf(ww.y,h2[4*q+1], fmaf(ww.z,h2[4*q+2], fmaf(ww.w,h2[4*q+3], acc))));
    }
    const float dz1 = acc * dact_h(h1[k]);
    const float4* w1r = (const float4*)(sm + OFF_W1 + k*16);
    de0 = fma4(dz1, w1r[0], de0);
    de1 = fma4(dz1, w1r[1], de1);
    de2 = fma4(dz1, w1r[2], de2);
    de3 = fma4(dz1, w1r[3], de3);
  }

  // ---- re-gather corners -> gradient wrt g ----
  float gx = 0.0f, gy = 0.0f, gz = 0.0f;
  #pragma unroll
  for (int dx = 0; dx < 2; ++dx){
    const float wxv = dx ? fx : (1.0f - fx);
    #pragma unroll
    for (int dy = 0; dy < 2; ++dy){
      const float wyv = dy ? fy : (1.0f - fy);
      const float4* gp = (const float4*)(grid + base + dx*SX + dy*SY);
      float s0 = dot4(gp[0],de0)+dot4(gp[1],de1)+dot4(gp[2],de2)+dot4(gp[3],de3);
      float s1 = dot4(gp[4],de0)+dot4(gp[5],de1)+dot4(gp[6],de2)+dot4(gp[7],de3);
      float sc = fmaf(fz, s1 - s0, s0);           // (1-fz)*s0 + fz*s1
      gz = fmaf(wxv*wyv, s1 - s0, gz);
      gx += dx ? wyv*sc : -wyv*sc;
      gy += dy ? wxv*sc : -wxv*sc;
    }
  }
  const float SCALE = 0.5f*(float)(GG-1)/1.3f;
  const float Gx = ax ? gx*SCALE : 0.0f;
  const float Gy = ay ? gy*SCALE : 0.0f;
  const float Gz = az ? gz*SCALE : 0.0f;
  out_grads[3*p+0] = Gx;
  out_grads[3*p+1] = Gy;
  out_grads[3*p+2] = Gz;

  const float nn = sqrtf(Gx*Gx + Gy*Gy + Gz*Gz);
  const float inv = 1.0f / fmaxf(nn, 1e-12f);
  const float nx = Gx*inv, ny = Gy*inv, nz = Gz*inv;

  // ---- color MLP: [feat(15), normals(3)] -> 64 -> 64 -> 3, relu/relu/sigmoid ----
  float cin[18];
  #pragma unroll
  for (int i = 0; i < 15; ++i) cin[i] = feat[i];
  cin[15]=nx; cin[16]=ny; cin[17]=nz;

  float c1[64];
  #pragma unroll
  for (int j = 0; j < 64; ++j){
    const float* w = sm + OFF_CW1 + j*18;
    float z = sm[OFF_CB1+j];
    #pragma unroll
    for (int i = 0; i < 18; ++i) z = fmaf(w[i], cin[i], z);
    c1[j] = fmaxf(z, 0.0f);
  }
  float c2[64];
  #pragma unroll
  for (int j = 0; j < 64; ++j){
    const float4* w = (const float4*)(sm + OFF_CW2 + j*64);
    float z = sm[OFF_CB2+j];
    #pragma unroll
    for (int q = 0; q < 16; ++q){
      float4 ww = w[q];
      z = fmaf(ww.x,c1[4*q+0], fmaf(ww.y,c1[4*q+1], fmaf(ww.z,c1[4*q+2], fmaf(ww.w,c1[4*q+3], z))));
    }
    c2[j] = fmaxf(z, 0.0f);
  }
  float rgb[3];
  #pragma unroll
  for (int c = 0; c < 3; ++c){
    const float4* w = (const float4*)(sm + OFF_CW3 + c*64);
    float z = sm[OFF_CB3+c];
    #pragma unroll
    for (int q = 0; q < 16; ++q){
      float4 ww = w[q];
      z = fmaf(ww.x,c2[4*q+0], fmaf(ww.y,c2[4*q+1], fmaf(ww.z,c2[4*q+2], fmaf(ww.w,c2[4*q+3], z))));
    }
    rgb[c] = 1.0f / (1.0f + __expf(-z));
  }

  // ---- sigma (Laplace CDF) ----
  const float bet = 0.015f + fabsf(beta_p[0]);
  const float sgn = (sdf > 0.0f) ? 1.0f : ((sdf < 0.0f) ? -1.0f : 0.0f);
  float sigma = (0.5f + 0.5f*sgn*expm1f(-fabsf(sdf)/bet)) / bet;
  if (!mask) sigma = 0.0f;

  g_srgb[p] = make_float4(sigma, rgb[0], rgb[1], rgb[2]);
  g_nrm[p]  = make_float4(nx, ny, nz, 0.0f);
}

// ---- per-ray compositing: one warp per ray, 2 samples per lane ----
__global__ void __launch_bounds__(256)
k_render(const float* __restrict__ rdn,
         const unsigned* __restrict__ near_p, const unsigned* __restrict__ far_p,
         float* __restrict__ out)
{
  const int gt = blockIdx.x*256 + threadIdx.x;
  const int r = gt >> 5;
  const int lane = gt & 31;
  if (r >= RR) return;

  const float nearf = decode_scalar(near_p);
  const float farf  = decode_scalar(far_p);
  const float span  = farf - nearf;
  const float dt    = span * (1.0f/64.0f);

  const int p0 = r*64 + lane, p1 = p0 + 32;
  float4 a0 = g_srgb[p0], a1 = g_srgb[p1];
  float4 n0 = g_nrm[p0],  n1 = g_nrm[p1];
  const float dd0 = a0.x * dt;
  const float dd1 = a1.x * dt;

  // inclusive scans
  float cs0 = dd0;
  #pragma unroll
  for (int o = 1; o < 32; o <<= 1){ float v = __shfl_up_sync(0xffffffffu, cs0, o); if (lane >= o) cs0 += v; }
  const float tot0 = __shfl_sync(0xffffffffu, cs0, 31);
  float cs1 = dd1;
  #pragma unroll
  for (int o = 1; o < 32; o <<= 1){ float v = __shfl_up_sync(0xffffffffu, cs1, o); if (lane >= o) cs1 += v; }
  cs1 += tot0;

  const float T0 = __expf(dd0 - cs0);
  const float T1 = __expf(dd1 - cs1);
  const float w0 = (1.0f - __expf(-dd0)) * T0;
  const float w1 = (1.0f - __expf(-dd1)) * T1;
  const float tm0 = nearf + span * (((float)lane + 0.5f)  * (1.0f/64.0f));
  const float tm1 = nearf + span * (((float)lane + 32.5f) * (1.0f/64.0f));

  float v0 = w0*a0.y + w1*a1.y;     // R
  float v1 = w0*a0.z + w1*a1.z;     // G
  float v2 = w0*a0.w + w1*a1.w;     // B
  float v3 = w0*tm0  + w1*tm1;      // depth (pre-division)
  float v4 = w0*n0.x + w1*n1.x;
  float v5 = w0*n0.y + w1*n1.y;
  float v6 = w0*n0.z + w1*n1.z;
  float v7 = w0 + w1;               // acc

  #pragma unroll
  for (int o = 16; o > 0; o >>= 1){
    v0 += __shfl_down_sync(0xffffffffu, v0, o);
    v1 += __shfl_down_sync(0xffffffffu, v1, o);
    v2 += __shfl_down_sync(0xffffffffu, v2, o);
    v3 += __shfl_down_sync(0xffffffffu, v3, o);
    v4 += __shfl_down_sync(0xffffffffu, v4, o);
    v5 += __shfl_down_sync(0xffffffffu, v5, o);
    v6 += __shfl_down_sync(0xffffffffu, v6, o);
    v7 += __shfl_down_sync(0xffffffffu, v7, o);
  }
  if (lane == 0){
    float* op = out + r*8;
    op[0]=v0; op[1]=v1; op[2]=v2;
    op[3]=v3 / rdn[r];
    op[4]=v4; op[5]=v5; op[6]=v6; op[7]=v7;
  }
}

extern "C" void kernel_launch(void* const* d_in, const int* in_sizes, int n_in,
                              void* d_out, int out_size)
{
  const float* rays_o = (const float*)d_in[0];
  const float* rays_d = (const float*)d_in[1];
  const float* rdn    = (const float*)d_in[2];
  const float* grid   = (const float*)d_in[3];
  const float* sw1 = (const float*)d_in[4];
  const float* sb1 = (const float*)d_in[5];
  const float* sw2 = (const float*)d_in[6];
  const float* sb2 = (const float*)d_in[7];
  const float* sw3 = (const float*)d_in[8];
  const float* sb3 = (const float*)d_in[9];
  const float* cw1 = (const float*)d_in[10];
  const float* cb1 = (const float*)d_in[11];
  const float* cw2 = (const float*)d_in[12];
  const float* cb2 = (const float*)d_in[13];
  const float* cw3 = (const float*)d_in[14];
  const float* cb3 = (const float*)d_in[15];
  const float* beta = (const float*)d_in[16];
  const unsigned* nearp = (const unsigned*)d_in[17];
  const unsigned* farp  = (const unsigned*)d_in[18];

  float* out = (float*)d_out;
  float* out_grads = out + RR*8;   // output = [rendered (R,8), sdf_grads (R*S,3)]

  const int smem_bytes = SM_FLOATS * (int)sizeof(float);
  cudaFuncSetAttribute(k_points, cudaFuncAttributeMaxDynamicSharedMemorySize, smem_bytes);

  k_points<<<NPTS/128, 128, smem_bytes>>>(
      rays_o, rays_d, grid,
      sw1, sb1, sw2, sb2, sw3, sb3,
      cw1, cb1, cw2, cb2, cw3, cb3,
      beta, nearp, farp, out_grads);

  k_render<<<(RR*32)/256, 256>>>(rdn, nearp, farp, out);
}

// round 3
// speedup vs baseline: 2.6643x; 2.6643x over previous
#include <cuda_runtime.h>

#define RR 16384
#define SS 64
#define GG 128
#define EE 16
#define NPTS (RR*SS)
#define SX (GG*GG*EE)
#define SY (GG*EE)
#define TPB 256

// ---- scratch (per-point) ----
__device__ float4 g_srgb[NPTS];   // (sigma, r, g, b)
__device__ float4 g_nrm[NPTS];    // (nx, ny, nz, 0)

__device__ __forceinline__ float decode_scalar(const unsigned* p){
  unsigned u = *p;
  if (u == 0u) return 0.0f;
  if ((u >> 23) == 0u) return (float)(int)u;   // small integer bit pattern
  return __uint_as_float(u);
}
__device__ __forceinline__ float dot4(float4 a, float4 b){
  return fmaf(a.x,b.x, fmaf(a.y,b.y, fmaf(a.z,b.z, a.w*b.w)));
}
__device__ __forceinline__ float4 fma4(float w, float4 v, float4 a){
  a.x=fmaf(w,v.x,a.x); a.y=fmaf(w,v.y,a.y); a.z=fmaf(w,v.z,a.z); a.w=fmaf(w,v.w,a.w); return a;
}
// softplus(100 z)/100, numerically stable
__device__ __forceinline__ float softplus100(float z){
  float y = 100.0f*z;
  float t = __expf(-fabsf(y));
  return (fmaxf(y,0.0f) + __logf(1.0f + t)) * 0.01f;
}
// sigmoid(100 z) recovered from h = softplus(100z)/100
__device__ __forceinline__ float dact_h(float h){ return 1.0f - __expf(-100.0f*h); }

// ---- shared layout (float offsets) ----
#define OFF_W1    0      // 1024  (64x16 row-major)
#define OFF_B1    1024   // 64
#define OFF_W2T   1088   // 4096  ([k][j] = w2[j][k])
#define OFF_B2    5184   // 64
#define OFF_W3    5248   // 1024  (16x64 row-major)
#define OFF_B3    6272   // 16
#define OFF_CW1P  6288   // 1536  (64x24, rows zero-padded from 18)
#define OFF_CB1   7824   // 64
#define OFF_CW2T  7888   // 4096  ([k][j])
#define OFF_CB2   11984  // 64
#define OFF_CW3   12048  // 192   (3x64)
#define OFF_CB3   12240  // 3
#define OFF_S1    12244  // 64*256 per-thread scratch (sigmoid of layer1 preact)
#define SM_FLOATS (OFF_S1 + 64*TPB)

__global__ void __launch_bounds__(TPB, 2)
k_points(const float* __restrict__ rays_o, const float* __restrict__ rays_d,
         const float* __restrict__ grid,
         const float* __restrict__ sw1, const float* __restrict__ sb1,
         const float* __restrict__ sw2, const float* __restrict__ sb2,
         const float* __restrict__ sw3, const float* __restrict__ sb3,
         const float* __restrict__ cw1, const float* __restrict__ cb1,
         const float* __restrict__ cw2, const float* __restrict__ cb2,
         const float* __restrict__ cw3, const float* __restrict__ cb3,
         const float* __restrict__ beta_p,
         const unsigned* __restrict__ near_p, const unsigned* __restrict__ far_p,
         float* __restrict__ out_grads)
{
  extern __shared__ float sm[];
  const int tid = threadIdx.x;

  // ---- cooperative weight staging (transpose W2, CW2; pad CW1) ----
  for (int i = tid; i < 1024; i += TPB){ sm[OFF_W1+i]=sw1[i]; sm[OFF_W3+i]=sw3[i]; }
  for (int i = tid; i < 4096; i += TPB){
    int j = i >> 6, k = i & 63;
    sm[OFF_W2T  + k*64 + j] = sw2[i];
    sm[OFF_CW2T + k*64 + j] = cw2[i];
  }
  for (int i = tid; i < 1536; i += TPB) sm[OFF_CW1P+i] = 0.0f;
  for (int i = tid; i < 192;  i += TPB) sm[OFF_CW3+i]=cw3[i];
  if (tid < 64){ sm[OFF_B1+tid]=sb1[tid]; sm[OFF_B2+tid]=sb2[tid];
                 sm[OFF_CB1+tid]=cb1[tid]; sm[OFF_CB2+tid]=cb2[tid]; }
  if (tid < 16) sm[OFF_B3+tid]=sb3[tid];
  if (tid < 3)  sm[OFF_CB3+tid]=cb3[tid];
  __syncthreads();
  for (int i = tid; i < 1152; i += TPB){
    int j = i / 18, c = i - j*18;
    sm[OFF_CW1P + j*24 + c] = cw1[i];
  }
  __syncthreads();

  const int p = blockIdx.x*TPB + tid;
  const int r = p >> 6;
  const int s = p & 63;
  float* s1p = sm + OFF_S1 + tid;   // stride TPB per k

  const float nearf = decode_scalar(near_p);
  const float farf  = decode_scalar(far_p);
  const float span  = farf - nearf;
  const float tm = nearf + span * ((s + 0.5f) * (1.0f/64.0f));

  const float px = fmaf(tm, rays_d[3*r+0], rays_o[3*r+0]);
  const float py = fmaf(tm, rays_d[3*r+1], rays_o[3*r+1]);
  const float pz = fmaf(tm, rays_d[3*r+2], rays_o[3*r+2]);

  // ---- trilinear setup ----
  const float HALF = 0.5f*(float)(GG-1);
  float grx = (px*(1.0f/1.3f) + 1.0f)*HALF;
  float gry = (py*(1.0f/1.3f) + 1.0f)*HALF;
  float grz = (pz*(1.0f/1.3f) + 1.0f)*HALF;
  const float GM1 = (float)(GG-1);
  const bool ax = (grx >= 0.0f) && (grx <= GM1);
  const bool ay = (gry >= 0.0f) && (gry <= GM1);
  const bool az = (grz >= 0.0f) && (grz <= GM1);
  const bool mask = ax && ay && az;
  float gcx = fminf(fmaxf(grx,0.0f), GM1);
  float gcy = fminf(fmaxf(gry,0.0f), GM1);
  float gcz = fminf(fmaxf(grz,0.0f), GM1);
  int ix = min((int)gcx, GG-2);
  int iy = min((int)gcy, GG-2);
  int iz = min((int)gcz, GG-2);
  const float fx = gcx - (float)ix;
  const float fy = gcy - (float)iy;
  const float fz = gcz - (float)iz;
  const int base = ((ix*GG + iy)*GG + iz)*EE;

  // ---- forward gather: emb[16] as 4x float4 ----
  float4 e0={0,0,0,0}, e1=e0, e2=e0, e3=e0;
  #pragma unroll
  for (int dx = 0; dx < 2; ++dx){
    const float wxv = dx ? fx : (1.0f - fx);
    #pragma unroll
    for (int dy = 0; dy < 2; ++dy){
      const float wyv = dy ? fy : (1.0f - fy);
      const float4* gp = (const float4*)(grid + base + dx*SX + dy*SY);
      const float w0 = wxv*wyv*(1.0f - fz);
      const float w1 = wxv*wyv*fz;
      e0=fma4(w0,gp[0],e0); e1=fma4(w0,gp[1],e1); e2=fma4(w0,gp[2],e2); e3=fma4(w0,gp[3],e3);
      e0=fma4(w1,gp[4],e0); e1=fma4(w1,gp[5],e1); e2=fma4(w1,gp[6],e2); e3=fma4(w1,gp[7],e3);
    }
  }

  // ---- SDF layers 1+2 fused: stream h1_k, accumulate z2[64] ----
  float h2[64];
  #pragma unroll
  for (int j = 0; j < 64; ++j) h2[j] = sm[OFF_B2+j];

  #pragma unroll 2
  for (int k = 0; k < 64; ++k){
    const float4* w1r = (const float4*)(sm + OFF_W1 + k*16);
    float za = dot4(w1r[0],e0) + dot4(w1r[2],e2);
    float zb = dot4(w1r[1],e1) + dot4(w1r[3],e3);
    float h = softplus100(sm[OFF_B1+k] + za + zb);
    s1p[k*TPB] = dact_h(h);                     // sigmoid(100 z1_k) for backward
    const float4* w2r = (const float4*)(sm + OFF_W2T + k*64);
    #pragma unroll
    for (int q = 0; q < 16; ++q){
      float4 w = w2r[q];
      h2[4*q+0] = fmaf(w.x, h, h2[4*q+0]);
      h2[4*q+1] = fmaf(w.y, h, h2[4*q+1]);
      h2[4*q+2] = fmaf(w.z, h, h2[4*q+2]);
      h2[4*q+3] = fmaf(w.w, h, h2[4*q+3]);
    }
  }
  // activation in place: h2 := softplus100(z2)
  #pragma unroll
  for (int j = 0; j < 64; ++j) h2[j] = softplus100(h2[j]);

  // ---- layer 3: 16 outputs ----
  float sdf;
  float feat[15];
  #pragma unroll
  for (int c = 0; c < 16; ++c){
    const float4* w = (const float4*)(sm + OFF_W3 + c*64);
    float a0=0.f, a1=0.f, a2=0.f, a3=0.f;
    #pragma unroll
    for (int q = 0; q < 16; ++q){
      float4 ww = w[q];
      a0 = fmaf(ww.x, h2[4*q+0], a0);
      a1 = fmaf(ww.y, h2[4*q+1], a1);
      a2 = fmaf(ww.z, h2[4*q+2], a2);
      a3 = fmaf(ww.w, h2[4*q+3], a3);
    }
    float z = sm[OFF_B3+c] + ((a0+a1)+(a2+a3));
    if (c == 0) sdf = z; else feat[c-1] = z;
  }

  // ---- backward: g2_j = W3[0][j] * sigmoid(100 z2_j)  (overwrite h2) ----
  #pragma unroll
  for (int j = 0; j < 64; ++j) h2[j] = sm[OFF_W3 + j] * dact_h(h2[j]);

  float4 de0={0,0,0,0}, de1=de0, de2=de0, de3=de0;
  #pragma unroll 2
  for (int k = 0; k < 64; ++k){
    const float4* w2r = (const float4*)(sm + OFF_W2T + k*64);   // column k of W2
    float a0=0.f, a1=0.f, a2=0.f, a3=0.f;
    #pragma unroll
    for (int q = 0; q < 16; ++q){
      float4 w = w2r[q];
      a0 = fmaf(w.x, h2[4*q+0], a0);
      a1 = fmaf(w.y, h2[4*q+1], a1);
      a2 = fmaf(w.z, h2[4*q+2], a2);
      a3 = fmaf(w.w, h2[4*q+3], a3);
    }
    const float dz1 = ((a0+a1)+(a2+a3)) * s1p[k*TPB];
    const float4* w1r = (const float4*)(sm + OFF_W1 + k*16);
    de0 = fma4(dz1, w1r[0], de0);
    de1 = fma4(dz1, w1r[1], de1);
    de2 = fma4(dz1, w1r[2], de2);
    de3 = fma4(dz1, w1r[3], de3);
  }

  // ---- re-gather corners -> gradient wrt grid coords ----
  float gx = 0.0f, gy = 0.0f, gz = 0.0f;
  #pragma unroll
  for (int dx = 0; dx < 2; ++dx){
    const float wxv = dx ? fx : (1.0f - fx);
    #pragma unroll
    for (int dy = 0; dy < 2; ++dy){
      const float wyv = dy ? fy : (1.0f - fy);
      const float4* gp = (const float4*)(grid + base + dx*SX + dy*SY);
      float sA = dot4(gp[0],de0)+dot4(gp[1],de1)+dot4(gp[2],de2)+dot4(gp[3],de3);
      float sB = dot4(gp[4],de0)+dot4(gp[5],de1)+dot4(gp[6],de2)+dot4(gp[7],de3);
      float sc = fmaf(fz, sB - sA, sA);
      gz = fmaf(wxv*wyv, sB - sA, gz);
      gx += dx ? wyv*sc : -wyv*sc;
      gy += dy ? wxv*sc : -wxv*sc;
    }
  }
  const float SCALE = 0.5f*(float)(GG-1)/1.3f;
  const float Gx = ax ? gx*SCALE : 0.0f;
  const float Gy = ay ? gy*SCALE : 0.0f;
  const float Gz = az ? gz*SCALE : 0.0f;
  out_grads[3*p+0] = Gx;
  out_grads[3*p+1] = Gy;
  out_grads[3*p+2] = Gz;

  const float nn = sqrtf(Gx*Gx + Gy*Gy + Gz*Gz);
  const float inv = 1.0f / fmaxf(nn, 1e-12f);
  const float nx = Gx*inv, ny = Gy*inv, nz = Gz*inv;

  // ---- color MLP: stream c1_j, accumulate z2c[64] ----
  float c4a[6][4];                      // cin padded to 24
  #pragma unroll
  for (int i = 0; i < 15; ++i) c4a[i>>2][i&3] = feat[i];
  c4a[3][3]=nx; c4a[4][0]=ny; c4a[4][1]=nz;
  c4a[4][2]=0.f; c4a[4][3]=0.f;
  c4a[5][0]=0.f; c4a[5][1]=0.f; c4a[5][2]=0.f; c4a[5][3]=0.f;
  float4 ci0 = make_float4(c4a[0][0],c4a[0][1],c4a[0][2],c4a[0][3]);
  float4 ci1 = make_float4(c4a[1][0],c4a[1][1],c4a[1][2],c4a[1][3]);
  float4 ci2 = make_float4(c4a[2][0],c4a[2][1],c4a[2][2],c4a[2][3]);
  float4 ci3 = make_float4(c4a[3][0],c4a[3][1],c4a[3][2],c4a[3][3]);
  float4 ci4 = make_float4(c4a[4][0],c4a[4][1],c4a[4][2],c4a[4][3]);

  float c2[64];
  #pragma unroll
  for (int j = 0; j < 64; ++j) c2[j] = sm[OFF_CB2+j];

  #pragma unroll 2
  for (int j = 0; j < 64; ++j){
    const float4* w = (const float4*)(sm + OFF_CW1P + j*24);
    float za = dot4(w[0],ci0) + dot4(w[2],ci2);
    float zb = dot4(w[1],ci1) + dot4(w[3],ci3);
    float z = sm[OFF_CB1+j] + za + zb + dot4(w[4],ci4);
    float c1 = fmaxf(z, 0.0f);
    const float4* wt = (const float4*)(sm + OFF_CW2T + j*64);
    #pragma unroll
    for (int q = 0; q < 16; ++q){
      float4 ww = wt[q];
      c2[4*q+0] = fmaf(ww.x, c1, c2[4*q+0]);
      c2[4*q+1] = fmaf(ww.y, c1, c2[4*q+1]);
      c2[4*q+2] = fmaf(ww.z, c1, c2[4*q+2]);
      c2[4*q+3] = fmaf(ww.w, c1, c2[4*q+3]);
    }
  }
  #pragma unroll
  for (int j = 0; j < 64; ++j) c2[j] = fmaxf(c2[j], 0.0f);

  float rgb[3];
  #pragma unroll
  for (int c = 0; c < 3; ++c){
    const float4* w = (const float4*)(sm + OFF_CW3 + c*64);
    float a0=0.f, a1=0.f, a2=0.f, a3=0.f;
    #pragma unroll
    for (int q = 0; q < 16; ++q){
      float4 ww = w[q];
      a0 = fmaf(ww.x, c2[4*q+0], a0);
      a1 = fmaf(ww.y, c2[4*q+1], a1);
      a2 = fmaf(ww.z, c2[4*q+2], a2);
      a3 = fmaf(ww.w, c2[4*q+3], a3);
    }
    float z = sm[OFF_CB3+c] + ((a0+a1)+(a2+a3));
    rgb[c] = 1.0f / (1.0f + __expf(-z));
  }

  // ---- sigma (Laplace CDF) ----
  const float bet = 0.015f + fabsf(beta_p[0]);
  const float sgn = (sdf > 0.0f) ? 1.0f : ((sdf < 0.0f) ? -1.0f : 0.0f);
  float sigma = (0.5f + 0.5f*sgn*expm1f(-fabsf(sdf)/bet)) / bet;
  if (!mask) sigma = 0.0f;

  g_srgb[p] = make_float4(sigma, rgb[0], rgb[1], rgb[2]);
  g_nrm[p]  = make_float4(nx, ny, nz, 0.0f);
}

// ---- per-ray compositing: one warp per ray, 2 samples per lane ----
__global__ void __launch_bounds__(256)
k_render(const float* __restrict__ rdn,
         const unsigned* __restrict__ near_p, const unsigned* __restrict__ far_p,
         float* __restrict__ out)
{
  const int gt = blockIdx.x*256 + threadIdx.x;
  const int r = gt >> 5;
  const int lane = gt & 31;
  if (r >= RR) return;

  const float nearf = decode_scalar(near_p);
  const float farf  = decode_scalar(far_p);
  const float span  = farf - nearf;
  const float dt    = span * (1.0f/64.0f);

  const int p0 = r*64 + lane, p1 = p0 + 32;
  float4 a0 = g_srgb[p0], a1 = g_srgb[p1];
  float4 n0 = g_nrm[p0],  n1 = g_nrm[p1];
  const float dd0 = a0.x * dt;
  const float dd1 = a1.x * dt;

  float cs0 = dd0;
  #pragma unroll
  for (int o = 1; o < 32; o <<= 1){ float v = __shfl_up_sync(0xffffffffu, cs0, o); if (lane >= o) cs0 += v; }
  const float tot0 = __shfl_sync(0xffffffffu, cs0, 31);
  float cs1 = dd1;
  #pragma unroll
  for (int o = 1; o < 32; o <<= 1){ float v = __shfl_up_sync(0xffffffffu, cs1, o); if (lane >= o) cs1 += v; }
  cs1 += tot0;

  const float T0 = __expf(dd0 - cs0);
  const float T1 = __expf(dd1 - cs1);
  const float w0 = (1.0f - __expf(-dd0)) * T0;
  const float w1 = (1.0f - __expf(-dd1)) * T1;
  const float tm0 = nearf + span * (((float)lane + 0.5f)  * (1.0f/64.0f));
  const float tm1 = nearf + span * (((float)lane + 32.5f) * (1.0f/64.0f));

  float v0 = w0*a0.y + w1*a1.y;
  float v1 = w0*a0.z + w1*a1.z;
  float v2 = w0*a0.w + w1*a1.w;
  float v3 = w0*tm0  + w1*tm1;
  float v4 = w0*n0.x + w1*n1.x;
  float v5 = w0*n0.y + w1*n1.y;
  float v6 = w0*n0.z + w1*n1.z;
  float v7 = w0 + w1;

  #pragma unroll
  for (int o = 16; o > 0; o >>= 1){
    v0 += __shfl_down_sync(0xffffffffu, v0, o);
    v1 += __shfl_down_sync(0xffffffffu, v1, o);
    v2 += __shfl_down_sync(0xffffffffu, v2, o);
    v3 += __shfl_down_sync(0xffffffffu, v3, o);
    v4 += __shfl_down_sync(0xffffffffu, v4, o);
    v5 += __shfl_down_sync(0xffffffffu, v5, o);
    v6 += __shfl_down_sync(0xffffffffu, v6, o);
    v7 += __shfl_down_sync(0xffffffffu, v7, o);
  }
  if (lane == 0){
    float* op = out + r*8;
    op[0]=v0; op[1]=v1; op[2]=v2;
    op[3]=v3 / rdn[r];
    op[4]=v4; op[5]=v5; op[6]=v6; op[7]=v7;
  }
}

extern "C" void kernel_launch(void* const* d_in, const int* in_sizes, int n_in,
                              void* d_out, int out_size)
{
  const float* rays_o = (const float*)d_in[0];
  const float* rays_d = (const float*)d_in[1];
  const float* rdn    = (const float*)d_in[2];
  const float* grid   = (const float*)d_in[3];
  const float* sw1 = (const float*)d_in[4];
  const float* sb1 = (const float*)d_in[5];
  const float* sw2 = (const float*)d_in[6];
  const float* sb2 = (const float*)d_in[7];
  const float* sw3 = (const float*)d_in[8];
  const float* sb3 = (const float*)d_in[9];
  const float* cw1 = (const float*)d_in[10];
  const float* cb1 = (const float*)d_in[11];
  const float* cw2 = (const float*)d_in[12];
  const float* cb2 = (const float*)d_in[13];
  const float* cw3 = (const float*)d_in[14];
  const float* cb3 = (const float*)d_in[15];
  const float* beta = (const float*)d_in[16];
  const unsigned* nearp = (const unsigned*)d_in[17];
  const unsigned* farp  = (const unsigned*)d_in[18];

  float* out = (float*)d_out;
  float* out_grads = out + RR*8;   // output = [rendered (R,8), sdf_grads (R*S,3)]

  const int smem_bytes = SM_FLOATS * (int)sizeof(float);
  static int configured = -1;
  cudaFuncSetAttribute(k_points, cudaFuncAttributeMaxDynamicSharedMemorySize, smem_bytes);
  (void)configured;

  k_points<<<NPTS/TPB, TPB, smem_bytes>>>(
      rays_o, rays_d, grid,
      sw1, sb1, sw2, sb2, sw3, sb3,
      cw1, cb1, cw2, cb2, cw3, cb3,
      beta, nearp, farp, out_grads);

  k_render<<<(RR*32)/256, 256>>>(rdn, nearp, farp, out);
}

// round 4
// speedup vs baseline: 4.4431x; 1.6676x over previous
#include <cuda_runtime.h>

#define RR 16384
#define SS 64
#define GG 128
#define EE 16
#define NPTS (RR*SS)
#define SX (GG*GG*EE)
#define SY (GG*EE)
#define TPB 128
#define PPT 2            // points per thread

// ---- scratch (per-point) ----
__device__ float4 g_srgb[NPTS];   // (sigma, r, g, b)
__device__ float4 g_nrm[NPTS];    // (nx, ny, nz, 0)

__device__ __forceinline__ float decode_scalar(const unsigned* p){
  unsigned u = *p;
  if (u == 0u) return 0.0f;
  if ((u >> 23) == 0u) return (float)(int)u;   // small integer bit pattern
  return __uint_as_float(u);
}
__device__ __forceinline__ float dot4(float4 a, float4 b){
  return fmaf(a.x,b.x, fmaf(a.y,b.y, fmaf(a.z,b.z, a.w*b.w)));
}
__device__ __forceinline__ float4 fma4(float w, float4 v, float4 a){
  a.x=fmaf(w,v.x,a.x); a.y=fmaf(w,v.y,a.y); a.z=fmaf(w,v.z,a.z); a.w=fmaf(w,v.w,a.w); return a;
}
__device__ __forceinline__ float softplus100(float z){
  float y = 100.0f*z;
  float t = __expf(-fabsf(y));
  return (fmaxf(y,0.0f) + __logf(1.0f + t)) * 0.01f;
}
// sigmoid(100 z)
__device__ __forceinline__ float sig100(float z){
  return 1.0f / (1.0f + __expf(-100.0f*z));
}
// sigmoid(100 z) from h = softplus100(z)
__device__ __forceinline__ float dact_h(float h){ return 1.0f - __expf(-100.0f*h); }

// ---- shared layout (float offsets) ----
#define OFF_W1    0      // 1024  (64x16 row-major)
#define OFF_B1    1024   // 64
#define OFF_W2T   1088   // 4096  ([k][j] = w2[j][k])
#define OFF_B2    5184   // 64
#define OFF_W3    5248   // 1024  (16x64 row-major)
#define OFF_B3    6272   // 16
#define OFF_CW1P  6288   // 1536  (64x24, rows zero-padded from 18)
#define OFF_CB1   7824   // 64
#define OFF_CW2T  7888   // 4096  ([k][j])
#define OFF_CB2   11984  // 64
#define OFF_CW3   12048  // 192   (3x64)
#define OFF_CB3   12240  // 3
#define SM_FLOATS 12244

struct Geo {
  float fx, fy, fz;
  int base;
  bool ax, ay, az;
};

__global__ void __launch_bounds__(TPB, 2)
k_points(const float* __restrict__ rays_o, const float* __restrict__ rays_d,
         const float* __restrict__ grid,
         const float* __restrict__ sw1, const float* __restrict__ sb1,
         const float* __restrict__ sw2, const float* __restrict__ sb2,
         const float* __restrict__ sw3, const float* __restrict__ sb3,
         const float* __restrict__ cw1, const float* __restrict__ cb1,
         const float* __restrict__ cw2, const float* __restrict__ cb2,
         const float* __restrict__ cw3, const float* __restrict__ cb3,
         const float* __restrict__ beta_p,
         const unsigned* __restrict__ near_p, const unsigned* __restrict__ far_p,
         float* __restrict__ out_grads)
{
  extern __shared__ float sm[];
  const int tid = threadIdx.x;

  // ---- cooperative weight staging ----
  for (int i = tid; i < 1024; i += TPB){ sm[OFF_W1+i]=sw1[i]; sm[OFF_W3+i]=sw3[i]; }
  for (int i = tid; i < 4096; i += TPB){
    int j = i >> 6, k = i & 63;
    sm[OFF_W2T  + k*64 + j] = sw2[i];
    sm[OFF_CW2T + k*64 + j] = cw2[i];
  }
  for (int i = tid; i < 1536; i += TPB) sm[OFF_CW1P+i] = 0.0f;
  for (int i = tid; i < 192;  i += TPB) sm[OFF_CW3+i]=cw3[i];
  if (tid < 64){ sm[OFF_B1+tid]=sb1[tid]; sm[OFF_B2+tid]=sb2[tid];
                 sm[OFF_CB1+tid]=cb1[tid]; sm[OFF_CB2+tid]=cb2[tid]; }
  if (tid < 16) sm[OFF_B3+tid]=sb3[tid];
  if (tid < 3)  sm[OFF_CB3+tid]=cb3[tid];
  __syncthreads();
  for (int i = tid; i < 1152; i += TPB){
    int j = i / 18, c = i - j*18;
    sm[OFF_CW1P + j*24 + c] = cw1[i];
  }
  __syncthreads();

  const int pA = blockIdx.x*(TPB*PPT) + tid;
  const int pB = pA + TPB;

  const float nearf = decode_scalar(near_p);
  const float farf  = decode_scalar(far_p);
  const float span  = farf - nearf;

  // ---- geometry + forward gather for both points ----
  Geo gA, gB;
  float4 eA0,eA1,eA2,eA3, eB0,eB1,eB2,eB3;

  #pragma unroll
  for (int pi = 0; pi < PPT; ++pi){
    const int p = pi ? pB : pA;
    const int r = p >> 6;
    const int s = p & 63;
    const float tm = nearf + span * ((s + 0.5f) * (1.0f/64.0f));
    const float px = fmaf(tm, rays_d[3*r+0], rays_o[3*r+0]);
    const float py = fmaf(tm, rays_d[3*r+1], rays_o[3*r+1]);
    const float pz = fmaf(tm, rays_d[3*r+2], rays_o[3*r+2]);

    const float HALF = 0.5f*(float)(GG-1);
    float grx = (px*(1.0f/1.3f) + 1.0f)*HALF;
    float gry = (py*(1.0f/1.3f) + 1.0f)*HALF;
    float grz = (pz*(1.0f/1.3f) + 1.0f)*HALF;
    const float GM1 = (float)(GG-1);
    Geo g;
    g.ax = (grx >= 0.0f) && (grx <= GM1);
    g.ay = (gry >= 0.0f) && (gry <= GM1);
    g.az = (grz >= 0.0f) && (grz <= GM1);
    float gcx = fminf(fmaxf(grx,0.0f), GM1);
    float gcy = fminf(fmaxf(gry,0.0f), GM1);
    float gcz = fminf(fmaxf(grz,0.0f), GM1);
    int ix = min((int)gcx, GG-2);
    int iy = min((int)gcy, GG-2);
    int iz = min((int)gcz, GG-2);
    g.fx = gcx - (float)ix;
    g.fy = gcy - (float)iy;
    g.fz = gcz - (float)iz;
    g.base = ((ix*GG + iy)*GG + iz)*EE;

    float4 e0={0,0,0,0}, e1=e0, e2=e0, e3=e0;
    #pragma unroll
    for (int dx = 0; dx < 2; ++dx){
      const float wxv = dx ? g.fx : (1.0f - g.fx);
      #pragma unroll
      for (int dy = 0; dy < 2; ++dy){
        const float wyv = dy ? g.fy : (1.0f - g.fy);
        const float4* gp = (const float4*)(grid + g.base + dx*SX + dy*SY);
        const float w0 = wxv*wyv*(1.0f - g.fz);
        const float w1 = wxv*wyv*g.fz;
        e0=fma4(w0,gp[0],e0); e1=fma4(w0,gp[1],e1); e2=fma4(w0,gp[2],e2); e3=fma4(w0,gp[3],e3);
        e0=fma4(w1,gp[4],e0); e1=fma4(w1,gp[5],e1); e2=fma4(w1,gp[6],e2); e3=fma4(w1,gp[7],e3);
      }
    }
    if (pi){ gB=g; eB0=e0; eB1=e1; eB2=e2; eB3=e3; }
    else   { gA=g; eA0=e0; eA1=e1; eA2=e2; eA3=e3; }
  }

  // ---- SDF layers 1+2 fused (both points share weight loads) ----
  float h2A[64], h2B[64];
  #pragma unroll
  for (int j = 0; j < 64; ++j){ float b = sm[OFF_B2+j]; h2A[j]=b; h2B[j]=b; }

  #pragma unroll 1
  for (int k = 0; k < 64; ++k){
    const float4* w1r = (const float4*)(sm + OFF_W1 + k*16);
    float4 w10=w1r[0], w11=w1r[1], w12=w1r[2], w13=w1r[3];
    const float b1 = sm[OFF_B1+k];
    float zA = b1 + (dot4(w10,eA0)+dot4(w12,eA2)) + (dot4(w11,eA1)+dot4(w13,eA3));
    float zB = b1 + (dot4(w10,eB0)+dot4(w12,eB2)) + (dot4(w11,eB1)+dot4(w13,eB3));
    float hA = softplus100(zA);
    float hB = softplus100(zB);
    const float4* w2r = (const float4*)(sm + OFF_W2T + k*64);
    #pragma unroll
    for (int q = 0; q < 16; ++q){
      float4 w = w2r[q];
      h2A[4*q+0] = fmaf(w.x, hA, h2A[4*q+0]);
      h2A[4*q+1] = fmaf(w.y, hA, h2A[4*q+1]);
      h2A[4*q+2] = fmaf(w.z, hA, h2A[4*q+2]);
      h2A[4*q+3] = fmaf(w.w, hA, h2A[4*q+3]);
      h2B[4*q+0] = fmaf(w.x, hB, h2B[4*q+0]);
      h2B[4*q+1] = fmaf(w.y, hB, h2B[4*q+1]);
      h2B[4*q+2] = fmaf(w.z, hB, h2B[4*q+2]);
      h2B[4*q+3] = fmaf(w.w, hB, h2B[4*q+3]);
    }
  }
  #pragma unroll
  for (int j = 0; j < 64; ++j){ h2A[j] = softplus100(h2A[j]); h2B[j] = softplus100(h2B[j]); }

  // ---- layer 3 (both points) ----
  float sdfA, sdfB;
  float featA[15], featB[15];
  #pragma unroll 1
  for (int c = 0; c < 16; ++c){
    const float4* w = (const float4*)(sm + OFF_W3 + c*64);
    float a0=0.f,a1=0.f,a2=0.f,a3=0.f, b0=0.f,b1=0.f,b2=0.f,b3=0.f;
    #pragma unroll
    for (int q = 0; q < 16; ++q){
      float4 ww = w[q];
      a0 = fmaf(ww.x, h2A[4*q+0], a0);
      a1 = fmaf(ww.y, h2A[4*q+1], a1);
      a2 = fmaf(ww.z, h2A[4*q+2], a2);
      a3 = fmaf(ww.w, h2A[4*q+3], a3);
      b0 = fmaf(ww.x, h2B[4*q+0], b0);
      b1 = fmaf(ww.y, h2B[4*q+1], b1);
      b2 = fmaf(ww.z, h2B[4*q+2], b2);
      b3 = fmaf(ww.w, h2B[4*q+3], b3);
    }
    float bias = sm[OFF_B3+c];
    float zA = bias + ((a0+a1)+(a2+a3));
    float zB = bias + ((b0+b1)+(b2+b3));
    if (c == 0){ sdfA = zA; sdfB = zB; }
    else { featA[c-1] = zA; featB[c-1] = zB; }
  }

  // ---- backward: g2 = W3[0][:] * sigmoid(100 z2), overwrite h2 ----
  #pragma unroll
  for (int j = 0; j < 64; ++j){
    float w3j = sm[OFF_W3 + j];
    h2A[j] = w3j * dact_h(h2A[j]);
    h2B[j] = w3j * dact_h(h2B[j]);
  }

  float4 dA0={0,0,0,0}, dA1=dA0, dA2=dA0, dA3=dA0;
  float4 dB0={0,0,0,0}, dB1=dB0, dB2=dB0, dB3=dB0;
  #pragma unroll 1
  for (int k = 0; k < 64; ++k){
    const float4* w2r = (const float4*)(sm + OFF_W2T + k*64);
    float a0=0.f,a1=0.f,a2=0.f,a3=0.f, b0=0.f,b1=0.f,b2=0.f,b3=0.f;
    #pragma unroll
    for (int q = 0; q < 16; ++q){
      float4 w = w2r[q];
      a0 = fmaf(w.x, h2A[4*q+0], a0);
      a1 = fmaf(w.y, h2A[4*q+1], a1);
      a2 = fmaf(w.z, h2A[4*q+2], a2);
      a3 = fmaf(w.w, h2A[4*q+3], a3);
      b0 = fmaf(w.x, h2B[4*q+0], b0);
      b1 = fmaf(w.y, h2B[4*q+1], b1);
      b2 = fmaf(w.z, h2B[4*q+2], b2);
      b3 = fmaf(w.w, h2B[4*q+3], b3);
    }
    const float4* w1r = (const float4*)(sm + OFF_W1 + k*16);
    float4 w10=w1r[0], w11=w1r[1], w12=w1r[2], w13=w1r[3];
    const float bb = sm[OFF_B1+k];
    // recompute layer-1 preact -> sigmoid (saves the smem scratch round-trip)
    float zA = bb + (dot4(w10,eA0)+dot4(w12,eA2)) + (dot4(w11,eA1)+dot4(w13,eA3));
    float zB = bb + (dot4(w10,eB0)+dot4(w12,eB2)) + (dot4(w11,eB1)+dot4(w13,eB3));
    const float dzA = ((a0+a1)+(a2+a3)) * sig100(zA);
    const float dzB = ((b0+b1)+(b2+b3)) * sig100(zB);
    dA0 = fma4(dzA, w10, dA0); dA1 = fma4(dzA, w11, dA1);
    dA2 = fma4(dzA, w12, dA2); dA3 = fma4(dzA, w13, dA3);
    dB0 = fma4(dzB, w10, dB0); dB1 = fma4(dzB, w11, dB1);
    dB2 = fma4(dzB, w12, dB2); dB3 = fma4(dzB, w13, dB3);
  }

  // ---- re-gather corners -> spatial gradient; normals; store grads ----
  float nxA,nyA,nzA, nxB,nyB,nzB;
  #pragma unroll
  for (int pi = 0; pi < PPT; ++pi){
    const Geo g = pi ? gB : gA;
    const float4 d0 = pi ? dB0 : dA0;
    const float4 d1 = pi ? dB1 : dA1;
    const float4 d2 = pi ? dB2 : dA2;
    const float4 d3 = pi ? dB3 : dA3;
    float gx=0.f, gy=0.f, gz=0.f;
    #pragma unroll
    for (int dx = 0; dx < 2; ++dx){
      const float wxv = dx ? g.fx : (1.0f - g.fx);
      #pragma unroll
      for (int dy = 0; dy < 2; ++dy){
        const float wyv = dy ? g.fy : (1.0f - g.fy);
        const float4* gp = (const float4*)(grid + g.base + dx*SX + dy*SY);
        float sA = dot4(gp[0],d0)+dot4(gp[1],d1)+dot4(gp[2],d2)+dot4(gp[3],d3);
        float sB = dot4(gp[4],d0)+dot4(gp[5],d1)+dot4(gp[6],d2)+dot4(gp[7],d3);
        float sc = fmaf(g.fz, sB - sA, sA);
        gz = fmaf(wxv*wyv, sB - sA, gz);
        gx += dx ? wyv*sc : -wyv*sc;
        gy += dy ? wxv*sc : -wxv*sc;
      }
    }
    const float SCALE = 0.5f*(float)(GG-1)/1.3f;
    const float Gx = g.ax ? gx*SCALE : 0.0f;
    const float Gy = g.ay ? gy*SCALE : 0.0f;
    const float Gz = g.az ? gz*SCALE : 0.0f;
    const int p = pi ? pB : pA;
    out_grads[3*p+0] = Gx;
    out_grads[3*p+1] = Gy;
    out_grads[3*p+2] = Gz;
    const float nn = sqrtf(Gx*Gx + Gy*Gy + Gz*Gz);
    const float inv = 1.0f / fmaxf(nn, 1e-12f);
    if (pi){ nxB=Gx*inv; nyB=Gy*inv; nzB=Gz*inv; }
    else   { nxA=Gx*inv; nyA=Gy*inv; nzA=Gz*inv; }
  }

  // ---- color MLP, layers 1+2 fused (reuse h2A/h2B as c2 accumulators) ----
  float4 cA0 = make_float4(featA[0],featA[1],featA[2],featA[3]);
  float4 cA1 = make_float4(featA[4],featA[5],featA[6],featA[7]);
  float4 cA2 = make_float4(featA[8],featA[9],featA[10],featA[11]);
  float4 cA3 = make_float4(featA[12],featA[13],featA[14],nxA);
  float4 cA4 = make_float4(nyA,nzA,0.f,0.f);
  float4 cB0 = make_float4(featB[0],featB[1],featB[2],featB[3]);
  float4 cB1 = make_float4(featB[4],featB[5],featB[6],featB[7]);
  float4 cB2 = make_float4(featB[8],featB[9],featB[10],featB[11]);
  float4 cB3 = make_float4(featB[12],featB[13],featB[14],nxB);
  float4 cB4 = make_float4(nyB,nzB,0.f,0.f);

  #pragma unroll
  for (int j = 0; j < 64; ++j){ float b = sm[OFF_CB2+j]; h2A[j]=b; h2B[j]=b; }

  #pragma unroll 1
  for (int j = 0; j < 64; ++j){
    const float4* w = (const float4*)(sm + OFF_CW1P + j*24);
    float4 w0=w[0], w1=w[1], w2=w[2], w3=w[3], w4=w[4];
    const float bias = sm[OFF_CB1+j];
    float zA = bias + (dot4(w0,cA0)+dot4(w2,cA2)) + (dot4(w1,cA1)+dot4(w3,cA3)) + dot4(w4,cA4);
    float zB = bias + (dot4(w0,cB0)+dot4(w2,cB2)) + (dot4(w1,cB1)+dot4(w3,cB3)) + dot4(w4,cB4);
    float c1A = fmaxf(zA, 0.0f);
    float c1B = fmaxf(zB, 0.0f);
    const float4* wt = (const float4*)(sm + OFF_CW2T + j*64);
    #pragma unroll
    for (int q = 0; q < 16; ++q){
      float4 ww = wt[q];
      h2A[4*q+0] = fmaf(ww.x, c1A, h2A[4*q+0]);
      h2A[4*q+1] = fmaf(ww.y, c1A, h2A[4*q+1]);
      h2A[4*q+2] = fmaf(ww.z, c1A, h2A[4*q+2]);
      h2A[4*q+3] = fmaf(ww.w, c1A, h2A[4*q+3]);
      h2B[4*q+0] = fmaf(ww.x, c1B, h2B[4*q+0]);
      h2B[4*q+1] = fmaf(ww.y, c1B, h2B[4*q+1]);
      h2B[4*q+2] = fmaf(ww.z, c1B, h2B[4*q+2]);
      h2B[4*q+3] = fmaf(ww.w, c1B, h2B[4*q+3]);
    }
  }
  #pragma unroll
  for (int j = 0; j < 64; ++j){ h2A[j] = fmaxf(h2A[j],0.0f); h2B[j] = fmaxf(h2B[j],0.0f); }

  float rgbA[3], rgbB[3];
  #pragma unroll 1
  for (int c = 0; c < 3; ++c){
    const float4* w = (const float4*)(sm + OFF_CW3 + c*64);
    float a0=0.f,a1=0.f,a2=0.f,a3=0.f, b0=0.f,b1=0.f,b2=0.f,b3=0.f;
    #pragma unroll
    for (int q = 0; q < 16; ++q){
      float4 ww = w[q];
      a0 = fmaf(ww.x, h2A[4*q+0], a0);
      a1 = fmaf(ww.y, h2A[4*q+1], a1);
      a2 = fmaf(ww.z, h2A[4*q+2], a2);
      a3 = fmaf(ww.w, h2A[4*q+3], a3);
      b0 = fmaf(ww.x, h2B[4*q+0], b0);
      b1 = fmaf(ww.y, h2B[4*q+1], b1);
      b2 = fmaf(ww.z, h2B[4*q+2], b2);
      b3 = fmaf(ww.w, h2B[4*q+3], b3);
    }
    float bias = sm[OFF_CB3+c];
    rgbA[c] = 1.0f / (1.0f + __expf(-(bias + ((a0+a1)+(a2+a3)))));
    rgbB[c] = 1.0f / (1.0f + __expf(-(bias + ((b0+b1)+(b2+b3)))));
  }

  // ---- sigma (Laplace CDF) + stores ----
  const float bet = 0.015f + fabsf(beta_p[0]);
  {
    const float s = sdfA;
    const float sgn = (s > 0.0f) ? 1.0f : ((s < 0.0f) ? -1.0f : 0.0f);
    float sigma = (0.5f + 0.5f*sgn*expm1f(-fabsf(s)/bet)) / bet;
    if (!(gA.ax && gA.ay && gA.az)) sigma = 0.0f;
    g_srgb[pA] = make_float4(sigma, rgbA[0], rgbA[1], rgbA[2]);
    g_nrm[pA]  = make_float4(nxA, nyA, nzA, 0.0f);
  }
  {
    const float s = sdfB;
    const float sgn = (s > 0.0f) ? 1.0f : ((s < 0.0f) ? -1.0f : 0.0f);
    float sigma = (0.5f + 0.5f*sgn*expm1f(-fabsf(s)/bet)) / bet;
    if (!(gB.ax && gB.ay && gB.az)) sigma = 0.0f;
    g_srgb[pB] = make_float4(sigma, rgbB[0], rgbB[1], rgbB[2]);
    g_nrm[pB]  = make_float4(nxB, nyB, nzB, 0.0f);
  }
}

// ---- per-ray compositing: one warp per ray, 2 samples per lane ----
__global__ void __launch_bounds__(256)
k_render(const float* __restrict__ rdn,
         const unsigned* __restrict__ near_p, const unsigned* __restrict__ far_p,
         float* __restrict__ out)
{
  const int gt = blockIdx.x*256 + threadIdx.x;
  const int r = gt >> 5;
  const int lane = gt & 31;
  if (r >= RR) return;

  const float nearf = decode_scalar(near_p);
  const float farf  = decode_scalar(far_p);
  const float span  = farf - nearf;
  const float dt    = span * (1.0f/64.0f);

  const int p0 = r*64 + lane, p1 = p0 + 32;
  float4 a0 = g_srgb[p0], a1 = g_srgb[p1];
  float4 n0 = g_nrm[p0],  n1 = g_nrm[p1];
  const float dd0 = a0.x * dt;
  const float dd1 = a1.x * dt;

  float cs0 = dd0;
  #pragma unroll
  for (int o = 1; o < 32; o <<= 1){ float v = __shfl_up_sync(0xffffffffu, cs0, o); if (lane >= o) cs0 += v; }
  const float tot0 = __shfl_sync(0xffffffffu, cs0, 31);
  float cs1 = dd1;
  #pragma unroll
  for (int o = 1; o < 32; o <<= 1){ float v = __shfl_up_sync(0xffffffffu, cs1, o); if (lane >= o) cs1 += v; }
  cs1 += tot0;

  const float T0 = __expf(dd0 - cs0);
  const float T1 = __expf(dd1 - cs1);
  const float w0 = (1.0f - __expf(-dd0)) * T0;
  const float w1 = (1.0f - __expf(-dd1)) * T1;
  const float tm0 = nearf + span * (((float)lane + 0.5f)  * (1.0f/64.0f));
  const float tm1 = nearf + span * (((float)lane + 32.5f) * (1.0f/64.0f));

  float v0 = w0*a0.y + w1*a1.y;
  float v1 = w0*a0.z + w1*a1.z;
  float v2 = w0*a0.w + w1*a1.w;
  float v3 = w0*tm0  + w1*tm1;
  float v4 = w0*n0.x + w1*n1.x;
  float v5 = w0*n0.y + w1*n1.y;
  float v6 = w0*n0.z + w1*n1.z;
  float v7 = w0 + w1;

  #pragma unroll
  for (int o = 16; o > 0; o >>= 1){
    v0 += __shfl_down_sync(0xffffffffu, v0, o);
    v1 += __shfl_down_sync(0xffffffffu, v1, o);
    v2 += __shfl_down_sync(0xffffffffu, v2, o);
    v3 += __shfl_down_sync(0xffffffffu, v3, o);
    v4 += __shfl_down_sync(0xffffffffu, v4, o);
    v5 += __shfl_down_sync(0xffffffffu, v5, o);
    v6 += __shfl_down_sync(0xffffffffu, v6, o);
    v7 += __shfl_down_sync(0xffffffffu, v7, o);
  }
  if (lane == 0){
    float* op = out + r*8;
    op[0]=v0; op[1]=v1; op[2]=v2;
    op[3]=v3 / rdn[r];
    op[4]=v4; op[5]=v5; op[6]=v6; op[7]=v7;
  }
}

extern "C" void kernel_launch(void* const* d_in, const int* in_sizes, int n_in,
                              void* d_out, int out_size)
{
  const float* rays_o = (const float*)d_in[0];
  const float* rays_d = (const float*)d_in[1];
  const float* rdn    = (const float*)d_in[2];
  const float* grid   = (const float*)d_in[3];
  const float* sw1 = (const float*)d_in[4];
  const float* sb1 = (const float*)d_in[5];
  const float* sw2 = (const float*)d_in[6];
  const float* sb2 = (const float*)d_in[7];
  const float* sw3 = (const float*)d_in[8];
  const float* sb3 = (const float*)d_in[9];
  const float* cw1 = (const float*)d_in[10];
  const float* cb1 = (const float*)d_in[11];
  const float* cw2 = (const float*)d_in[12];
  const float* cb2 = (const float*)d_in[13];
  const float* cw3 = (const float*)d_in[14];
  const float* cb3 = (const float*)d_in[15];
  const float* beta = (const float*)d_in[16];
  const unsigned* nearp = (const unsigned*)d_in[17];
  const unsigned* farp  = (const unsigned*)d_in[18];

  float* out = (float*)d_out;
  float* out_grads = out + RR*8;   // output = [rendered (R,8), sdf_grads (R*S,3)]

  const int smem_bytes = SM_FLOATS * (int)sizeof(float);
  cudaFuncSetAttribute(k_points, cudaFuncAttributeMaxDynamicSharedMemorySize, smem_bytes);

  k_points<<<NPTS/(TPB*PPT), TPB, smem_bytes>>>(
      rays_o, rays_d, grid,
      sw1, sb1, sw2, sb2, sw3, sb3,
      cw1, cb1, cw2, cb2, cw3, cb3,
      beta, nearp, farp, out_grads);

  k_render<<<(RR*32)/256, 256>>>(rdn, nearp, farp, out);
}

// round 10
// speedup vs baseline: 5.1899x; 1.1681x over previous
#include <cuda_runtime.h>

#define RR 16384
#define SS 64
#define GG 128
#define EE 16
#define NPTS (RR*SS)
#define SX (GG*GG*EE)
#define SY (GG*EE)
#define TPB 128
#define PPT 2            // points per thread

// ---- scratch (per-point) ----
__device__ float4 g_srgb[NPTS];   // (sigma, r, g, b)
__device__ float4 g_nrm[NPTS];    // (nx, ny, nz, 0)

// Large streaming matrices live in the constant bank: warp-uniform loads go
// through the uniform-const port (LDCU) instead of the smem crossbar.
// k_prep writes them in-place through device pointers (cudaGetSymbolAddress);
// the region is plain device memory, so kernel stores to it are valid, and
// values are identical on every graph replay so cache staleness is harmless.
__constant__ __align__(16) float cW2T[4096];   // [k][j] = sw2[j][k]
__constant__ __align__(16) float cCW2T[4096];  // [k][j] = cw2[j][k]
__constant__ __align__(16) float cW3[1024];    // 16x64 row-major
__constant__ __align__(16) float cCW3[192];    // 3x64 row-major

__device__ __forceinline__ float decode_scalar(const unsigned* p){
  unsigned u = *p;
  if (u == 0u) return 0.0f;
  if ((u >> 23) == 0u) return (float)(int)u;   // small integer bit pattern
  return __uint_as_float(u);
}
__device__ __forceinline__ float dot4(float4 a, float4 b){
  return fmaf(a.x,b.x, fmaf(a.y,b.y, fmaf(a.z,b.z, a.w*b.w)));
}
__device__ __forceinline__ float4 fma4(float w, float4 v, float4 a){
  a.x=fmaf(w,v.x,a.x); a.y=fmaf(w,v.y,a.y); a.z=fmaf(w,v.z,a.z); a.w=fmaf(w,v.w,a.w); return a;
}
__device__ __forceinline__ float softplus100(float z){
  float y = 100.0f*z;
  float t = __expf(-fabsf(y));
  return (fmaxf(y,0.0f) + __logf(1.0f + t)) * 0.01f;
}
// sigmoid(100 z)
__device__ __forceinline__ float sig100(float z){
  return 1.0f / (1.0f + __expf(-100.0f*z));
}
// sigmoid(100 z) from h = softplus100(z)
__device__ __forceinline__ float dact_h(float h){ return 1.0f - __expf(-100.0f*h); }

// ---- shared layout (small arrays only; float offsets) ----
#define OFF_W1    0      // 1024  (64x16 row-major)
#define OFF_B1    1024   // 64
#define OFF_B2    1088   // 64
#define OFF_B3    1152   // 16
#define OFF_CW1P  1168   // 1536  (64x24, rows zero-padded from 18)
#define OFF_CB1   2704   // 64
#define OFF_CB2   2768   // 64
#define OFF_CB3   2832   // 3
#define SM_FLOATS 2836

struct Geo {
  float fx, fy, fz;
  int base;
  bool ax, ay, az;
};

// ---- prep: write transposed / raw weights directly into the constant bank ----
__global__ void k_prep(const float* __restrict__ sw2, const float* __restrict__ cw2,
                       const float* __restrict__ sw3, const float* __restrict__ cw3,
                       float* __restrict__ dW2T, float* __restrict__ dCW2T,
                       float* __restrict__ dW3, float* __restrict__ dCW3)
{
  for (int i = threadIdx.x; i < 4096; i += blockDim.x){
    int j = i >> 6, k = i & 63;
    dW2T [k*64 + j] = sw2[i];
    dCW2T[k*64 + j] = cw2[i];
  }
  for (int i = threadIdx.x; i < 1024; i += blockDim.x) dW3[i] = sw3[i];
  for (int i = threadIdx.x; i < 192;  i += blockDim.x) dCW3[i] = cw3[i];
}

__global__ void __launch_bounds__(TPB, 2)
k_points(const float* __restrict__ rays_o, const float* __restrict__ rays_d,
         const float* __restrict__ grid,
         const float* __restrict__ sw1, const float* __restrict__ sb1,
         const float* __restrict__ sb2, const float* __restrict__ sb3,
         const float* __restrict__ cw1, const float* __restrict__ cb1,
         const float* __restrict__ cb2, const float* __restrict__ cb3,
         const float* __restrict__ beta_p,
         const unsigned* __restrict__ near_p, const unsigned* __restrict__ far_p,
         float* __restrict__ out_grads)
{
  __shared__ float sm[SM_FLOATS];
  const int tid = threadIdx.x;

  // ---- cooperative staging of SMALL arrays ----
  for (int i = tid; i < 1024; i += TPB) sm[OFF_W1+i]=sw1[i];
  for (int i = tid; i < 1536; i += TPB) sm[OFF_CW1P+i] = 0.0f;
  if (tid < 64){ sm[OFF_B1+tid]=sb1[tid]; sm[OFF_B2+tid]=sb2[tid];
                 sm[OFF_CB1+tid]=cb1[tid]; sm[OFF_CB2+tid]=cb2[tid]; }
  if (tid < 16) sm[OFF_B3+tid]=sb3[tid];
  if (tid < 3)  sm[OFF_CB3+tid]=cb3[tid];
  __syncthreads();
  for (int i = tid; i < 1152; i += TPB){
    int j = i / 18, c = i - j*18;
    sm[OFF_CW1P + j*24 + c] = cw1[i];
  }
  __syncthreads();

  const int pA = blockIdx.x*(TPB*PPT) + tid;
  const int pB = pA + TPB;

  const float nearf = decode_scalar(near_p);
  const float farf  = decode_scalar(far_p);
  const float span  = farf - nearf;

  // ---- geometry + forward gather for both points ----
  Geo gA, gB;
  float4 eA0,eA1,eA2,eA3, eB0,eB1,eB2,eB3;

  #pragma unroll
  for (int pi = 0; pi < PPT; ++pi){
    const int p = pi ? pB : pA;
    const int r = p >> 6;
    const int s = p & 63;
    const float tm = nearf + span * ((s + 0.5f) * (1.0f/64.0f));
    const float px = fmaf(tm, rays_d[3*r+0], rays_o[3*r+0]);
    const float py = fmaf(tm, rays_d[3*r+1], rays_o[3*r+1]);
    const float pz = fmaf(tm, rays_d[3*r+2], rays_o[3*r+2]);

    const float HALF = 0.5f*(float)(GG-1);
    float grx = (px*(1.0f/1.3f) + 1.0f)*HALF;
    float gry = (py*(1.0f/1.3f) + 1.0f)*HALF;
    float grz = (pz*(1.0f/1.3f) + 1.0f)*HALF;
    const float GM1 = (float)(GG-1);
    Geo g;
    g.ax = (grx >= 0.0f) && (grx <= GM1);
    g.ay = (gry >= 0.0f) && (gry <= GM1);
    g.az = (grz >= 0.0f) && (grz <= GM1);
    float gcx = fminf(fmaxf(grx,0.0f), GM1);
    float gcy = fminf(fmaxf(gry,0.0f), GM1);
    float gcz = fminf(fmaxf(grz,0.0f), GM1);
    int ix = min((int)gcx, GG-2);
    int iy = min((int)gcy, GG-2);
    int iz = min((int)gcz, GG-2);
    g.fx = gcx - (float)ix;
    g.fy = gcy - (float)iy;
    g.fz = gcz - (float)iz;
    g.base = ((ix*GG + iy)*GG + iz)*EE;

    float4 e0={0,0,0,0}, e1=e0, e2=e0, e3=e0;
    #pragma unroll
    for (int dx = 0; dx < 2; ++dx){
      const float wxv = dx ? g.fx : (1.0f - g.fx);
      #pragma unroll
      for (int dy = 0; dy < 2; ++dy){
        const float wyv = dy ? g.fy : (1.0f - g.fy);
        const float4* gp = (const float4*)(grid + g.base + dx*SX + dy*SY);
        const float w0 = wxv*wyv*(1.0f - g.fz);
        const float w1 = wxv*wyv*g.fz;
        e0=fma4(w0,gp[0],e0); e1=fma4(w0,gp[1],e1); e2=fma4(w0,gp[2],e2); e3=fma4(w0,gp[3],e3);
        e0=fma4(w1,gp[4],e0); e1=fma4(w1,gp[5],e1); e2=fma4(w1,gp[6],e2); e3=fma4(w1,gp[7],e3);
      }
    }
    if (pi){ gB=g; eB0=e0; eB1=e1; eB2=e2; eB3=e3; }
    else   { gA=g; eA0=e0; eA1=e1; eA2=e2; eA3=e3; }
  }

  // ---- SDF layers 1+2 fused (W1/B1 smem, W2T const) ----
  float h2A[64], h2B[64];
  #pragma unroll
  for (int j = 0; j < 64; ++j){ float b = sm[OFF_B2+j]; h2A[j]=b; h2B[j]=b; }

  #pragma unroll 1
  for (int k = 0; k < 64; ++k){
    const float4* w1r = (const float4*)(sm + OFF_W1 + k*16);
    float4 w10=w1r[0], w11=w1r[1], w12=w1r[2], w13=w1r[3];
    const float b1 = sm[OFF_B1+k];
    float zA = b1 + (dot4(w10,eA0)+dot4(w12,eA2)) + (dot4(w11,eA1)+dot4(w13,eA3));
    float zB = b1 + (dot4(w10,eB0)+dot4(w12,eB2)) + (dot4(w11,eB1)+dot4(w13,eB3));
    float hA = softplus100(zA);
    float hB = softplus100(zB);
    const float4* w2r = (const float4*)(cW2T + k*64);
    #pragma unroll
    for (int q = 0; q < 16; ++q){
      float4 w = w2r[q];
      h2A[4*q+0] = fmaf(w.x, hA, h2A[4*q+0]);
      h2A[4*q+1] = fmaf(w.y, hA, h2A[4*q+1]);
      h2A[4*q+2] = fmaf(w.z, hA, h2A[4*q+2]);
      h2A[4*q+3] = fmaf(w.w, hA, h2A[4*q+3]);
      h2B[4*q+0] = fmaf(w.x, hB, h2B[4*q+0]);
      h2B[4*q+1] = fmaf(w.y, hB, h2B[4*q+1]);
      h2B[4*q+2] = fmaf(w.z, hB, h2B[4*q+2]);
      h2B[4*q+3] = fmaf(w.w, hB, h2B[4*q+3]);
    }
  }
  #pragma unroll
  for (int j = 0; j < 64; ++j){ h2A[j] = softplus100(h2A[j]); h2B[j] = softplus100(h2B[j]); }

  // ---- layer 3 (W3 const) ----
  float sdfA, sdfB;
  float featA[15], featB[15];
  #pragma unroll 1
  for (int c = 0; c < 16; ++c){
    const float4* w = (const float4*)(cW3 + c*64);
    float a0=0.f,a1=0.f,a2=0.f,a3=0.f, b0=0.f,b1=0.f,b2=0.f,b3=0.f;
    #pragma unroll
    for (int q = 0; q < 16; ++q){
      float4 ww = w[q];
      a0 = fmaf(ww.x, h2A[4*q+0], a0);
      a1 = fmaf(ww.y, h2A[4*q+1], a1);
      a2 = fmaf(ww.z, h2A[4*q+2], a2);
      a3 = fmaf(ww.w, h2A[4*q+3], a3);
      b0 = fmaf(ww.x, h2B[4*q+0], b0);
      b1 = fmaf(ww.y, h2B[4*q+1], b1);
      b2 = fmaf(ww.z, h2B[4*q+2], b2);
      b3 = fmaf(ww.w, h2B[4*q+3], b3);
    }
    float bias = sm[OFF_B3+c];
    float zA = bias + ((a0+a1)+(a2+a3));
    float zB = bias + ((b0+b1)+(b2+b3));
    if (c == 0){ sdfA = zA; sdfB = zB; }
    else { featA[c-1] = zA; featB[c-1] = zB; }
  }

  // ---- backward: g2 = W3[0][:] * sigmoid(100 z2), overwrite h2 ----
  #pragma unroll
  for (int j = 0; j < 64; ++j){
    float w3j = cW3[j];
    h2A[j] = w3j * dact_h(h2A[j]);
    h2B[j] = w3j * dact_h(h2B[j]);
  }

  float4 dA0={0,0,0,0}, dA1=dA0, dA2=dA0, dA3=dA0;
  float4 dB0={0,0,0,0}, dB1=dB0, dB2=dB0, dB3=dB0;
  #pragma unroll 1
  for (int k = 0; k < 64; ++k){
    const float4* w2r = (const float4*)(cW2T + k*64);
    float a0=0.f,a1=0.f,a2=0.f,a3=0.f, b0=0.f,b1=0.f,b2=0.f,b3=0.f;
    #pragma unroll
    for (int q = 0; q < 16; ++q){
      float4 w = w2r[q];
      a0 = fmaf(w.x, h2A[4*q+0], a0);
      a1 = fmaf(w.y, h2A[4*q+1], a1);
      a2 = fmaf(w.z, h2A[4*q+2], a2);
      a3 = fmaf(w.w, h2A[4*q+3], a3);
      b0 = fmaf(w.x, h2B[4*q+0], b0);
      b1 = fmaf(w.y, h2B[4*q+1], b1);
      b2 = fmaf(w.z, h2B[4*q+2], b2);
      b3 = fmaf(w.w, h2B[4*q+3], b3);
    }
    const float4* w1r = (const float4*)(sm + OFF_W1 + k*16);
    float4 w10=w1r[0], w11=w1r[1], w12=w1r[2], w13=w1r[3];
    const float bb = sm[OFF_B1+k];
    // recompute layer-1 preact -> sigmoid
    float zA = bb + (dot4(w10,eA0)+dot4(w12,eA2)) + (dot4(w11,eA1)+dot4(w13,eA3));
    float zB = bb + (dot4(w10,eB0)+dot4(w12,eB2)) + (dot4(w11,eB1)+dot4(w13,eB3));
    const float dzA = ((a0+a1)+(a2+a3)) * sig100(zA);
    const float dzB = ((b0+b1)+(b2+b3)) * sig100(zB);
    dA0 = fma4(dzA, w10, dA0); dA1 = fma4(dzA, w11, dA1);
    dA2 = fma4(dzA, w12, dA2); dA3 = fma4(dzA, w13, dA3);
    dB0 = fma4(dzB, w10, dB0); dB1 = fma4(dzB, w11, dB1);
    dB2 = fma4(dzB, w12, dB2); dB3 = fma4(dzB, w13, dB3);
  }

  // ---- re-gather corners -> spatial gradient; normals; store grads ----
  float nxA,nyA,nzA, nxB,nyB,nzB;
  #pragma unroll
  for (int pi = 0; pi < PPT; ++pi){
    const Geo g = pi ? gB : gA;
    const float4 d0 = pi ? dB0 : dA0;
    const float4 d1 = pi ? dB1 : dA1;
    const float4 d2 = pi ? dB2 : dA2;
    const float4 d3 = pi ? dB3 : dA3;
    float gx=0.f, gy=0.f, gz=0.f;
    #pragma unroll
    for (int dx = 0; dx < 2; ++dx){
      const float wxv = dx ? g.fx : (1.0f - g.fx);
      #pragma unroll
      for (int dy = 0; dy < 2; ++dy){
        const float wyv = dy ? g.fy : (1.0f - g.fy);
        const float4* gp = (const float4*)(grid + g.base + dx*SX + dy*SY);
        float sA = dot4(gp[0],d0)+dot4(gp[1],d1)+dot4(gp[2],d2)+dot4(gp[3],d3);
        float sB = dot4(gp[4],d0)+dot4(gp[5],d1)+dot4(gp[6],d2)+dot4(gp[7],d3);
        float sc = fmaf(g.fz, sB - sA, sA);
        gz = fmaf(wxv*wyv, sB - sA, gz);
        gx += dx ? wyv*sc : -wyv*sc;
        gy += dy ? wxv*sc : -wxv*sc;
      }
    }
    const float SCALE = 0.5f*(float)(GG-1)/1.3f;
    const float Gx = g.ax ? gx*SCALE : 0.0f;
    const float Gy = g.ay ? gy*SCALE : 0.0f;
    const float Gz = g.az ? gz*SCALE : 0.0f;
    const int p = pi ? pB : pA;
    out_grads[3*p+0] = Gx;
    out_grads[3*p+1] = Gy;
    out_grads[3*p+2] = Gz;
    const float nn = sqrtf(Gx*Gx + Gy*Gy + Gz*Gz);
    const float inv = 1.0f / fmaxf(nn, 1e-12f);
    if (pi){ nxB=Gx*inv; nyB=Gy*inv; nzB=Gz*inv; }
    else   { nxA=Gx*inv; nyA=Gy*inv; nzA=Gz*inv; }
  }

  // ---- color MLP, layers 1+2 fused (CW1P smem, CW2T const; reuse h2 as acc) ----
  float4 cA0 = make_float4(featA[0],featA[1],featA[2],featA[3]);
  float4 cA1 = make_float4(featA[4],featA[5],featA[6],featA[7]);
  float4 cA2 = make_float4(featA[8],featA[9],featA[10],featA[11]);
  float4 cA3 = make_float4(featA[12],featA[13],featA[14],nxA);
  float4 cA4 = make_float4(nyA,nzA,0.f,0.f);
  float4 cB0 = make_float4(featB[0],featB[1],featB[2],featB[3]);
  float4 cB1 = make_float4(featB[4],featB[5],featB[6],featB[7]);
  float4 cB2 = make_float4(featB[8],featB[9],featB[10],featB[11]);
  float4 cB3 = make_float4(featB[12],featB[13],featB[14],nxB);
  float4 cB4 = make_float4(nyB,nzB,0.f,0.f);

  #pragma unroll
  for (int j = 0; j < 64; ++j){ float b = sm[OFF_CB2+j]; h2A[j]=b; h2B[j]=b; }

  #pragma unroll 1
  for (int j = 0; j < 64; ++j){
    const float4* w = (const float4*)(sm + OFF_CW1P + j*24);
    float4 w0=w[0], w1=w[1], w2=w[2], w3=w[3], w4=w[4];
    const float bias = sm[OFF_CB1+j];
    float zA = bias + (dot4(w0,cA0)+dot4(w2,cA2)) + (dot4(w1,cA1)+dot4(w3,cA3)) + dot4(w4,cA4);
    float zB = bias + (dot4(w0,cB0)+dot4(w2,cB2)) + (dot4(w1,cB1)+dot4(w3,cB3)) + dot4(w4,cB4);
    float c1A = fmaxf(zA, 0.0f);
    float c1B = fmaxf(zB, 0.0f);
    const float4* wt = (const float4*)(cCW2T + j*64);
    #pragma unroll
    for (int q = 0; q < 16; ++q){
      float4 ww = wt[q];
      h2A[4*q+0] = fmaf(ww.x, c1A, h2A[4*q+0]);
      h2A[4*q+1] = fmaf(ww.y, c1A, h2A[4*q+1]);
      h2A[4*q+2] = fmaf(ww.z, c1A, h2A[4*q+2]);
      h2A[4*q+3] = fmaf(ww.w, c1A, h2A[4*q+3]);
      h2B[4*q+0] = fmaf(ww.x, c1B, h2B[4*q+0]);
      h2B[4*q+1] = fmaf(ww.y, c1B, h2B[4*q+1]);
      h2B[4*q+2] = fmaf(ww.z, c1B, h2B[4*q+2]);
      h2B[4*q+3] = fmaf(ww.w, c1B, h2B[4*q+3]);
    }
  }
  #pragma unroll
  for (int j = 0; j < 64; ++j){ h2A[j] = fmaxf(h2A[j],0.0f); h2B[j] = fmaxf(h2B[j],0.0f); }

  float rgbA[3], rgbB[3];
  #pragma unroll 1
  for (int c = 0; c < 3; ++c){
    const float4* w = (const float4*)(cCW3 + c*64);
    float a0=0.f,a1=0.f,a2=0.f,a3=0.f, b0=0.f,b1=0.f,b2=0.f,b3=0.f;
    #pragma unroll
    for (int q = 0; q < 16; ++q){
      float4 ww = w[q];
      a0 = fmaf(ww.x, h2A[4*q+0], a0);
      a1 = fmaf(ww.y, h2A[4*q+1], a1);
      a2 = fmaf(ww.z, h2A[4*q+2], a2);
      a3 = fmaf(ww.w, h2A[4*q+3], a3);
      b0 = fmaf(ww.x, h2B[4*q+0], b0);
      b1 = fmaf(ww.y, h2B[4*q+1], b1);
      b2 = fmaf(ww.z, h2B[4*q+2], b2);
      b3 = fmaf(ww.w, h2B[4*q+3], b3);
    }
    float bias = sm[OFF_CB3+c];
    rgbA[c] = 1.0f / (1.0f + __expf(-(bias + ((a0+a1)+(a2+a3)))));
    rgbB[c] = 1.0f / (1.0f + __expf(-(bias + ((b0+b1)+(b2+b3)))));
  }

  // ---- sigma (Laplace CDF) + stores ----
  const float bet = 0.015f + fabsf(beta_p[0]);
  {
    const float s = sdfA;
    const float sgn = (s > 0.0f) ? 1.0f : ((s < 0.0f) ? -1.0f : 0.0f);
    float sigma = (0.5f + 0.5f*sgn*expm1f(-fabsf(s)/bet)) / bet;
    if (!(gA.ax && gA.ay && gA.az)) sigma = 0.0f;
    g_srgb[pA] = make_float4(sigma, rgbA[0], rgbA[1], rgbA[2]);
    g_nrm[pA]  = make_float4(nxA, nyA, nzA, 0.0f);
  }
  {
    const float s = sdfB;
    const float sgn = (s > 0.0f) ? 1.0f : ((s < 0.0f) ? -1.0f : 0.0f);
    float sigma = (0.5f + 0.5f*sgn*expm1f(-fabsf(s)/bet)) / bet;
    if (!(gB.ax && gB.ay && gB.az)) sigma = 0.0f;
    g_srgb[pB] = make_float4(sigma, rgbB[0], rgbB[1], rgbB[2]);
    g_nrm[pB]  = make_float4(nxB, nyB, nzB, 0.0f);
  }
}

// ---- per-ray compositing: one warp per ray, 2 samples per lane ----
__global__ void __launch_bounds__(256)
k_render(const float* __restrict__ rdn,
         const unsigned* __restrict__ near_p, const unsigned* __restrict__ far_p,
         float* __restrict__ out)
{
  const int gt = blockIdx.x*256 + threadIdx.x;
  const int r = gt >> 5;
  const int lane = gt & 31;
  if (r >= RR) return;

  const float nearf = decode_scalar(near_p);
  const float farf  = decode_scalar(far_p);
  const float span  = farf - nearf;
  const float dt    = span * (1.0f/64.0f);

  const int p0 = r*64 + lane, p1 = p0 + 32;
  float4 a0 = g_srgb[p0], a1 = g_srgb[p1];
  float4 n0 = g_nrm[p0],  n1 = g_nrm[p1];
  const float dd0 = a0.x * dt;
  const float dd1 = a1.x * dt;

  float cs0 = dd0;
  #pragma unroll
  for (int o = 1; o < 32; o <<= 1){ float v = __shfl_up_sync(0xffffffffu, cs0, o); if (lane >= o) cs0 += v; }
  const float tot0 = __shfl_sync(0xffffffffu, cs0, 31);
  float cs1 = dd1;
  #pragma unroll
  for (int o = 1; o < 32; o <<= 1){ float v = __shfl_up_sync(0xffffffffu, cs1, o); if (lane >= o) cs1 += v; }
  cs1 += tot0;

  const float T0 = __expf(dd0 - cs0);
  const float T1 = __expf(dd1 - cs1);
  const float w0 = (1.0f - __expf(-dd0)) * T0;
  const float w1 = (1.0f - __expf(-dd1)) * T1;
  const float tm0 = nearf + span * (((float)lane + 0.5f)  * (1.0f/64.0f));
  const float tm1 = nearf + span * (((float)lane + 32.5f) * (1.0f/64.0f));

  float v0 = w0*a0.y + w1*a1.y;
  float v1 = w0*a0.z + w1*a1.z;
  float v2 = w0*a0.w + w1*a1.w;
  float v3 = w0*tm0  + w1*tm1;
  float v4 = w0*n0.x + w1*n1.x;
  float v5 = w0*n0.y + w1*n1.y;
  float v6 = w0*n0.z + w1*n1.z;
  float v7 = w0 + w1;

  #pragma unroll
  for (int o = 16; o > 0; o >>= 1){
    v0 += __shfl_down_sync(0xffffffffu, v0, o);
    v1 += __shfl_down_sync(0xffffffffu, v1, o);
    v2 += __shfl_down_sync(0xffffffffu, v2, o);
    v3 += __shfl_down_sync(0xffffffffu, v3, o);
    v4 += __shfl_down_sync(0xffffffffu, v4, o);
    v5 += __shfl_down_sync(0xffffffffu, v5, o);
    v6 += __shfl_down_sync(0xffffffffu, v6, o);
    v7 += __shfl_down_sync(0xffffffffu, v7, o);
  }
  if (lane == 0){
    float* op = out + r*8;
    op[0]=v0; op[1]=v1; op[2]=v2;
    op[3]=v3 / rdn[r];
    op[4]=v4; op[5]=v5; op[6]=v6; op[7]=v7;
  }
}

extern "C" void kernel_launch(void* const* d_in, const int* in_sizes, int n_in,
                              void* d_out, int out_size)
{
  const float* rays_o = (const float*)d_in[0];
  const float* rays_d = (const float*)d_in[1];
  const float* rdn    = (const float*)d_in[2];
  const float* grid   = (const float*)d_in[3];
  const float* sw1 = (const float*)d_in[4];
  const float* sb1 = (const float*)d_in[5];
  const float* sw2 = (const float*)d_in[6];
  const float* sb2 = (const float*)d_in[7];
  const float* sw3 = (const float*)d_in[8];
  const float* sb3 = (const float*)d_in[9];
  const float* cw1 = (const float*)d_in[10];
  const float* cb1 = (const float*)d_in[11];
  const float* cw2 = (const float*)d_in[12];
  const float* cb2 = (const float*)d_in[13];
  const float* cw3 = (const float*)d_in[14];
  const float* cb3 = (const float*)d_in[15];
  const float* beta = (const float*)d_in[16];
  const unsigned* nearp = (const unsigned*)d_in[17];
  const unsigned* farp  = (const unsigned*)d_in[18];

  float* out = (float*)d_out;
  float* out_grads = out + RR*8;   // output = [rendered (R,8), sdf_grads (R*S,3)]

  // Resolve constant-bank addresses (pure address queries; no stream work).
  void *w2t_p = nullptr, *cw2t_p = nullptr, *w3_p = nullptr, *cw3_p = nullptr;
  cudaGetSymbolAddress(&w2t_p,  cW2T);
  cudaGetSymbolAddress(&cw2t_p, cCW2T);
  cudaGetSymbolAddress(&w3_p,   cW3);
  cudaGetSymbolAddress(&cw3_p,  cCW3);

  // 1) prep kernel writes transposed weights straight into the constant bank
  k_prep<<<1, 256>>>(sw2, cw2, sw3, cw3,
                     (float*)w2t_p, (float*)cw2t_p, (float*)w3_p, (float*)cw3_p);

  // 2) main point kernel + compositing
  k_points<<<NPTS/(TPB*PPT), TPB>>>(
      rays_o, rays_d, grid,
      sw1, sb1, sb2, sb3,
      cw1, cb1, cb2, cb3,
      beta, nearp, farp, out_grads);

  k_render<<<(RR*32)/256, 256>>>(rdn, nearp, farp, out);
}

// round 12
// speedup vs baseline: 5.4410x; 1.0484x over previous
#include <cuda_runtime.h>

#define RR 16384
#define SS 64
#define GG 128
#define EE 16
#define NPTS (RR*SS)
#define SX (GG*GG*EE)
#define SY (GG*EE)
#define TPB 128
#define PPT 2            // points per thread

typedef unsigned long long u64;

// ---- scratch (per-point) ----
__device__ float4 g_srgb[NPTS];   // (sigma, r, g, b)
__device__ float4 g_nrm[NPTS];    // (nx, ny, nz, 0)

// Large streaming matrices in the constant bank (uniform-port loads).
__constant__ __align__(16) float cW2T[4096];   // [k][j] = sw2[j][k]
__constant__ __align__(16) float cCW2T[4096];  // [k][j] = cw2[j][k]
__constant__ __align__(16) float cW3[1024];    // 16x64 row-major
__constant__ __align__(16) float cCW3[192];    // 3x64 row-major

// ---- packed f32x2 helpers (Blackwell FFMA2 path, PTX-only) ----
__device__ __forceinline__ u64 pk2(float a, float b){
  u64 r; asm("mov.b64 %0, {%1,%2};" : "=l"(r) : "f"(a), "f"(b)); return r;
}
__device__ __forceinline__ float2 upk2(u64 v){
  float2 t; asm("mov.b64 {%0,%1}, %2;" : "=f"(t.x), "=f"(t.y) : "l"(v)); return t;
}
__device__ __forceinline__ u64 ffma2(u64 a, u64 b, u64 c){
  u64 r; asm("fma.rn.f32x2 %0, %1, %2, %3;" : "=l"(r) : "l"(a), "l"(b), "l"(c)); return r;
}
__device__ __forceinline__ u64 fmul2(u64 a, u64 b){
  u64 r; asm("mul.rn.f32x2 %0, %1, %2;" : "=l"(r) : "l"(a), "l"(b)); return r;
}

__device__ __forceinline__ float decode_scalar(const unsigned* p){
  unsigned u = *p;
  if (u == 0u) return 0.0f;
  if ((u >> 23) == 0u) return (float)(int)u;   // small integer bit pattern
  return __uint_as_float(u);
}
__device__ __forceinline__ float softplus100(float z){
  float y = 100.0f*z;
  float t = __expf(-fabsf(y));
  return (fmaxf(y,0.0f) + __logf(1.0f + t)) * 0.01f;
}
__device__ __forceinline__ float sig100(float z){
  return 1.0f / (1.0f + __expf(-100.0f*z));
}
__device__ __forceinline__ float dact_h(float h){ return 1.0f - __expf(-100.0f*h); }

// ---- shared layout (small arrays only; float offsets; all 16B-aligned) ----
#define OFF_W1    0      // 1024  (64x16 row-major)
#define OFF_B1    1024   // 64
#define OFF_B2    1088   // 64
#define OFF_B3    1152   // 16
#define OFF_CW1P  1168   // 1536  (64x24, rows zero-padded from 18)
#define OFF_CB1   2704   // 64
#define OFF_CB2   2768   // 64
#define OFF_CB3   2832   // 3
#define SM_FLOATS 2836

struct Geo {
  float fx, fy, fz;
  int base;
  bool ax, ay, az;
};

// ---- prep: write transposed / raw weights directly into the constant bank ----
__global__ void k_prep(const float* __restrict__ sw2, const float* __restrict__ cw2,
                       const float* __restrict__ sw3, const float* __restrict__ cw3,
                       float* __restrict__ dW2T, float* __restrict__ dCW2T,
                       float* __restrict__ dW3, float* __restrict__ dCW3)
{
  for (int i = threadIdx.x; i < 4096; i += blockDim.x){
    int j = i >> 6, k = i & 63;
    dW2T [k*64 + j] = sw2[i];
    dCW2T[k*64 + j] = cw2[i];
  }
  for (int i = threadIdx.x; i < 1024; i += blockDim.x) dW3[i] = sw3[i];
  for (int i = threadIdx.x; i < 192;  i += blockDim.x) dCW3[i] = cw3[i];
}

__global__ void __launch_bounds__(TPB, 2)
k_points(const float* __restrict__ rays_o, const float* __restrict__ rays_d,
         const float* __restrict__ grid,
         const float* __restrict__ sw1, const float* __restrict__ sb1,
         const float* __restrict__ sb2, const float* __restrict__ sb3,
         const float* __restrict__ cw1, const float* __restrict__ cb1,
         const float* __restrict__ cb2, const float* __restrict__ cb3,
         const float* __restrict__ beta_p,
         const unsigned* __restrict__ near_p, const unsigned* __restrict__ far_p,
         float* __restrict__ out_grads)
{
  __shared__ __align__(16) float sm[SM_FLOATS];
  const int tid = threadIdx.x;

  // ---- cooperative staging of SMALL arrays ----
  for (int i = tid; i < 1024; i += TPB) sm[OFF_W1+i]=sw1[i];
  for (int i = tid; i < 1536; i += TPB) sm[OFF_CW1P+i] = 0.0f;
  if (tid < 64){ sm[OFF_B1+tid]=sb1[tid]; sm[OFF_B2+tid]=sb2[tid];
                 sm[OFF_CB1+tid]=cb1[tid]; sm[OFF_CB2+tid]=cb2[tid]; }
  if (tid < 16) sm[OFF_B3+tid]=sb3[tid];
  if (tid < 3)  sm[OFF_CB3+tid]=cb3[tid];
  __syncthreads();
  for (int i = tid; i < 1152; i += TPB){
    int j = i / 18, c = i - j*18;
    sm[OFF_CW1P + j*24 + c] = cw1[i];
  }
  __syncthreads();

  const int pA = blockIdx.x*(TPB*PPT) + tid;
  const int pB = pA + TPB;

  const float nearf = decode_scalar(near_p);
  const float farf  = decode_scalar(far_p);
  const float span  = farf - nearf;

  // ---- geometry + forward gather (packed embeddings: 8 pairs per point) ----
  Geo gA, gB;
  u64 epA[8], epB[8];

  #pragma unroll
  for (int pi = 0; pi < PPT; ++pi){
    const int p = pi ? pB : pA;
    const int r = p >> 6;
    const int s = p & 63;
    const float tm = nearf + span * ((s + 0.5f) * (1.0f/64.0f));
    const float px = fmaf(tm, rays_d[3*r+0], rays_o[3*r+0]);
    const float py = fmaf(tm, rays_d[3*r+1], rays_o[3*r+1]);
    const float pz = fmaf(tm, rays_d[3*r+2], rays_o[3*r+2]);

    const float HALF = 0.5f*(float)(GG-1);
    float grx = (px*(1.0f/1.3f) + 1.0f)*HALF;
    float gry = (py*(1.0f/1.3f) + 1.0f)*HALF;
    float grz = (pz*(1.0f/1.3f) + 1.0f)*HALF;
    const float GM1 = (float)(GG-1);
    Geo g;
    g.ax = (grx >= 0.0f) && (grx <= GM1);
    g.ay = (gry >= 0.0f) && (gry <= GM1);
    g.az = (grz >= 0.0f) && (grz <= GM1);
    float gcx = fminf(fmaxf(grx,0.0f), GM1);
    float gcy = fminf(fmaxf(gry,0.0f), GM1);
    float gcz = fminf(fmaxf(grz,0.0f), GM1);
    int ix = min((int)gcx, GG-2);
    int iy = min((int)gcy, GG-2);
    int iz = min((int)gcz, GG-2);
    g.fx = gcx - (float)ix;
    g.fy = gcy - (float)iy;
    g.fz = gcz - (float)iz;
    g.base = ((ix*GG + iy)*GG + iz)*EE;

    u64 ep[8];
    #pragma unroll
    for (int i = 0; i < 8; ++i) ep[i] = 0ull;
    #pragma unroll
    for (int dx = 0; dx < 2; ++dx){
      const float wxv = dx ? g.fx : (1.0f - g.fx);
      #pragma unroll
      for (int dy = 0; dy < 2; ++dy){
        const float wyv = dy ? g.fy : (1.0f - g.fy);
        const ulonglong2* gp = (const ulonglong2*)(grid + g.base + dx*SX + dy*SY);
        const float w0 = wxv*wyv*(1.0f - g.fz);
        const float w1 = wxv*wyv*g.fz;
        const u64 w0p = pk2(w0,w0), w1p = pk2(w1,w1);
        #pragma unroll
        for (int i = 0; i < 4; ++i){
          ulonglong2 a = gp[i];
          ep[2*i]   = ffma2(w0p, a.x, ep[2*i]);
          ep[2*i+1] = ffma2(w0p, a.y, ep[2*i+1]);
        }
        #pragma unroll
        for (int i = 0; i < 4; ++i){
          ulonglong2 b = gp[4+i];
          ep[2*i]   = ffma2(w1p, b.x, ep[2*i]);
          ep[2*i+1] = ffma2(w1p, b.y, ep[2*i+1]);
        }
      }
    }
    if (pi){ gB=g; 
      #pragma unroll
      for (int i=0;i<8;++i) epB[i]=ep[i];
    } else { gA=g;
      #pragma unroll
      for (int i=0;i<8;++i) epA[i]=ep[i];
    }
  }

  // ---- SDF layers 1+2 fused: h2 accumulators packed (32 pairs per point) ----
  u64 h2A[32], h2B[32];
  #pragma unroll
  for (int j = 0; j < 32; ++j){
    u64 b = ((const u64*)(sm + OFF_B2))[j];
    h2A[j]=b; h2B[j]=b;
  }

  #pragma unroll 1
  for (int k = 0; k < 64; ++k){
    const ulonglong2* w1p = (const ulonglong2*)(sm + OFF_W1 + k*16);
    ulonglong2 wa=w1p[0], wb=w1p[1], wc=w1p[2], wd=w1p[3];
    const float b1 = sm[OFF_B1+k];
    u64 zA0=0ull, zA1=0ull, zB0=0ull, zB1=0ull;
    zA0=ffma2(wa.x,epA[0],zA0); zA1=ffma2(wa.y,epA[1],zA1);
    zA0=ffma2(wb.x,epA[2],zA0); zA1=ffma2(wb.y,epA[3],zA1);
    zA0=ffma2(wc.x,epA[4],zA0); zA1=ffma2(wc.y,epA[5],zA1);
    zA0=ffma2(wd.x,epA[6],zA0); zA1=ffma2(wd.y,epA[7],zA1);
    zB0=ffma2(wa.x,epB[0],zB0); zB1=ffma2(wa.y,epB[1],zB1);
    zB0=ffma2(wb.x,epB[2],zB0); zB1=ffma2(wb.y,epB[3],zB1);
    zB0=ffma2(wc.x,epB[4],zB0); zB1=ffma2(wc.y,epB[5],zB1);
    zB0=ffma2(wd.x,epB[6],zB0); zB1=ffma2(wd.y,epB[7],zB1);
    float2 a0=upk2(zA0), a1=upk2(zA1), b0=upk2(zB0), b1v=upk2(zB1);
    float zA = b1 + ((a0.x+a1.x)+(a0.y+a1.y));
    float zB = b1 + ((b0.x+b1v.x)+(b0.y+b1v.y));
    float hA = softplus100(zA);
    float hB = softplus100(zB);
    const u64 hAp = pk2(hA,hA), hBp = pk2(hB,hB);
    const ulonglong2* w2p = (const ulonglong2*)(cW2T + k*64);
    #pragma unroll
    for (int q = 0; q < 16; ++q){
      ulonglong2 wv = w2p[q];
      h2A[2*q]   = ffma2(wv.x, hAp, h2A[2*q]);
      h2A[2*q+1] = ffma2(wv.y, hAp, h2A[2*q+1]);
      h2B[2*q]   = ffma2(wv.x, hBp, h2B[2*q]);
      h2B[2*q+1] = ffma2(wv.y, hBp, h2B[2*q+1]);
    }
  }
  // activation in place
  #pragma unroll
  for (int j = 0; j < 32; ++j){
    float2 ta = upk2(h2A[j]); h2A[j] = pk2(softplus100(ta.x), softplus100(ta.y));
    float2 tb = upk2(h2B[j]); h2B[j] = pk2(softplus100(tb.x), softplus100(tb.y));
  }

  // ---- layer 3 (16 outputs, W3 const) ----
  float sdfA, sdfB;
  float featA[15], featB[15];
  #pragma unroll 1
  for (int c = 0; c < 16; ++c){
    const ulonglong2* w = (const ulonglong2*)(cW3 + c*64);
    u64 aA0=0ull,aA1=0ull,aB0=0ull,aB1=0ull;
    #pragma unroll
    for (int q = 0; q < 16; ++q){
      ulonglong2 wv = w[q];
      aA0 = ffma2(wv.x, h2A[2*q],   aA0);
      aA1 = ffma2(wv.y, h2A[2*q+1], aA1);
      aB0 = ffma2(wv.x, h2B[2*q],   aB0);
      aB1 = ffma2(wv.y, h2B[2*q+1], aB1);
    }
    float bias = sm[OFF_B3+c];
    float2 ta0=upk2(aA0), ta1=upk2(aA1), tb0=upk2(aB0), tb1=upk2(aB1);
    float zA = bias + ((ta0.x+ta1.x)+(ta0.y+ta1.y));
    float zB = bias + ((tb0.x+tb1.x)+(tb0.y+tb1.y));
    if (c == 0){ sdfA = zA; sdfB = zB; }
    else { featA[c-1] = zA; featB[c-1] = zB; }
  }

  // ---- backward: g2 = W3[0][:] * sigmoid(100 z2), overwrite h2 (packed) ----
  #pragma unroll
  for (int j = 0; j < 32; ++j){
    u64 w3p = ((const u64*)cW3)[j];
    float2 ta = upk2(h2A[j]);
    float2 tb = upk2(h2B[j]);
    h2A[j] = fmul2(w3p, pk2(dact_h(ta.x), dact_h(ta.y)));
    h2B[j] = fmul2(w3p, pk2(dact_h(tb.x), dact_h(tb.y)));
  }

  u64 deA[8], deB[8];
  #pragma unroll
  for (int i = 0; i < 8; ++i){ deA[i]=0ull; deB[i]=0ull; }

  #pragma unroll 1
  for (int k = 0; k < 64; ++k){
    const ulonglong2* w2p = (const ulonglong2*)(cW2T + k*64);
    u64 aA0=0ull,aA1=0ull,aB0=0ull,aB1=0ull;
    #pragma unroll
    for (int q = 0; q < 16; ++q){
      ulonglong2 wv = w2p[q];
      aA0 = ffma2(wv.x, h2A[2*q],   aA0);
      aA1 = ffma2(wv.y, h2A[2*q+1], aA1);
      aB0 = ffma2(wv.x, h2B[2*q],   aB0);
      aB1 = ffma2(wv.y, h2B[2*q+1], aB1);
    }
    float2 ta0=upk2(aA0), ta1=upk2(aA1), tb0=upk2(aB0), tb1=upk2(aB1);
    float sumA = (ta0.x+ta1.x)+(ta0.y+ta1.y);
    float sumB = (tb0.x+tb1.x)+(tb0.y+tb1.y);

    const ulonglong2* w1p = (const ulonglong2*)(sm + OFF_W1 + k*16);
    ulonglong2 wa=w1p[0], wb=w1p[1], wc=w1p[2], wd=w1p[3];
    const float bb = sm[OFF_B1+k];
    // recompute layer-1 preact -> sigmoid
    u64 zA0=0ull, zA1=0ull, zB0=0ull, zB1=0ull;
    zA0=ffma2(wa.x,epA[0],zA0); zA1=ffma2(wa.y,epA[1],zA1);
    zA0=ffma2(wb.x,epA[2],zA0); zA1=ffma2(wb.y,epA[3],zA1);
    zA0=ffma2(wc.x,epA[4],zA0); zA1=ffma2(wc.y,epA[5],zA1);
    zA0=ffma2(wd.x,epA[6],zA0); zA1=ffma2(wd.y,epA[7],zA1);
    zB0=ffma2(wa.x,epB[0],zB0); zB1=ffma2(wa.y,epB[1],zB1);
    zB0=ffma2(wb.x,epB[2],zB0); zB1=ffma2(wb.y,epB[3],zB1);
    zB0=ffma2(wc.x,epB[4],zB0); zB1=ffma2(wc.y,epB[5],zB1);
    zB0=ffma2(wd.x,epB[6],zB0); zB1=ffma2(wd.y,epB[7],zB1);
    float2 qa0=upk2(zA0), qa1=upk2(zA1), qb0=upk2(zB0), qb1=upk2(zB1);
    float zA = bb + ((qa0.x+qa1.x)+(qa0.y+qa1.y));
    float zB = bb + ((qb0.x+qb1.x)+(qb0.y+qb1.y));
    const float dzA = sumA * sig100(zA);
    const float dzB = sumB * sig100(zB);
    const u64 dzAp = pk2(dzA,dzA), dzBp = pk2(dzB,dzB);
    deA[0]=ffma2(dzAp,wa.x,deA[0]); deA[1]=ffma2(dzAp,wa.y,deA[1]);
    deA[2]=ffma2(dzAp,wb.x,deA[2]); deA[3]=ffma2(dzAp,wb.y,deA[3]);
    deA[4]=ffma2(dzAp,wc.x,deA[4]); deA[5]=ffma2(dzAp,wc.y,deA[5]);
    deA[6]=ffma2(dzAp,wd.x,deA[6]); deA[7]=ffma2(dzAp,wd.y,deA[7]);
    deB[0]=ffma2(dzBp,wa.x,deB[0]); deB[1]=ffma2(dzBp,wa.y,deB[1]);
    deB[2]=ffma2(dzBp,wb.x,deB[2]); deB[3]=ffma2(dzBp,wb.y,deB[3]);
    deB[4]=ffma2(dzBp,wc.x,deB[4]); deB[5]=ffma2(dzBp,wc.y,deB[5]);
    deB[6]=ffma2(dzBp,wd.x,deB[6]); deB[7]=ffma2(dzBp,wd.y,deB[7]);
  }

  // ---- re-gather corners (packed dot) -> spatial gradient; normals ----
  float nxA,nyA,nzA, nxB,nyB,nzB;
  #pragma unroll
  for (int pi = 0; pi < PPT; ++pi){
    const Geo g = pi ? gB : gA;
    const u64* de = pi ? deB : deA;
    float gx=0.f, gy=0.f, gz=0.f;
    #pragma unroll
    for (int dx = 0; dx < 2; ++dx){
      const float wxv = dx ? g.fx : (1.0f - g.fx);
      #pragma unroll
      for (int dy = 0; dy < 2; ++dy){
        const float wyv = dy ? g.fy : (1.0f - g.fy);
        const ulonglong2* gp = (const ulonglong2*)(grid + g.base + dx*SX + dy*SY);
        u64 acc0=0ull, acc1=0ull;
        #pragma unroll
        for (int i = 0; i < 4; ++i){
          ulonglong2 a = gp[i];
          acc0 = ffma2(a.x, de[2*i],   acc0);
          acc0 = ffma2(a.y, de[2*i+1], acc0);
        }
        #pragma unroll
        for (int i = 0; i < 4; ++i){
          ulonglong2 b = gp[4+i];
          acc1 = ffma2(b.x, de[2*i],   acc1);
          acc1 = ffma2(b.y, de[2*i+1], acc1);
        }
        float2 t0 = upk2(acc0), t1 = upk2(acc1);
        float sA = t0.x + t0.y;
        float sB = t1.x + t1.y;
        float sc = fmaf(g.fz, sB - sA, sA);
        gz = fmaf(wxv*wyv, sB - sA, gz);
        gx += dx ? wyv*sc : -wyv*sc;
        gy += dy ? wxv*sc : -wxv*sc;
      }
    }
    const float SCALE = 0.5f*(float)(GG-1)/1.3f;
    const float Gx = g.ax ? gx*SCALE : 0.0f;
    const float Gy = g.ay ? gy*SCALE : 0.0f;
    const float Gz = g.az ? gz*SCALE : 0.0f;
    const int p = pi ? pB : pA;
    out_grads[3*p+0] = Gx;
    out_grads[3*p+1] = Gy;
    out_grads[3*p+2] = Gz;
    const float nn = sqrtf(Gx*Gx + Gy*Gy + Gz*Gz);
    const float inv = 1.0f / fmaxf(nn, 1e-12f);
    if (pi){ nxB=Gx*inv; nyB=Gy*inv; nzB=Gz*inv; }
    else   { nxA=Gx*inv; nyA=Gy*inv; nzA=Gz*inv; }
  }

  // ---- color MLP (packed): cin as 9 pairs; reuse h2 as c2 accumulators ----
  u64 ciA[9], ciB[9];
  #pragma unroll
  for (int i = 0; i < 7; ++i){
    ciA[i] = pk2(featA[2*i], featA[2*i+1]);
    ciB[i] = pk2(featB[2*i], featB[2*i+1]);
  }
  ciA[7] = pk2(featA[14], nxA); ciA[8] = pk2(nyA, nzA);
  ciB[7] = pk2(featB[14], nxB); ciB[8] = pk2(nyB, nzB);

  #pragma unroll
  for (int j = 0; j < 32; ++j){
    u64 b = ((const u64*)(sm + OFF_CB2))[j];
    h2A[j]=b; h2B[j]=b;
  }

  #pragma unroll 1
  for (int j = 0; j < 64; ++j){
    const ulonglong2* w = (const ulonglong2*)(sm + OFF_CW1P + j*24);
    ulonglong2 wa=w[0], wb=w[1], wc=w[2], wd=w[3];
    u64 w8 = ((const u64*)(sm + OFF_CW1P + j*24))[8];
    const float bias = sm[OFF_CB1+j];
    u64 zA0=0ull, zA1=0ull, zB0=0ull, zB1=0ull;
    zA0=ffma2(wa.x,ciA[0],zA0); zA1=ffma2(wa.y,ciA[1],zA1);
    zA0=ffma2(wb.x,ciA[2],zA0); zA1=ffma2(wb.y,ciA[3],zA1);
    zA0=ffma2(wc.x,ciA[4],zA0); zA1=ffma2(wc.y,ciA[5],zA1);
    zA0=ffma2(wd.x,ciA[6],zA0); zA1=ffma2(wd.y,ciA[7],zA1);
    zA0=ffma2(w8,  ciA[8],zA0);
    zB0=ffma2(wa.x,ciB[0],zB0); zB1=ffma2(wa.y,ciB[1],zB1);
    zB0=ffma2(wb.x,ciB[2],zB0); zB1=ffma2(wb.y,ciB[3],zB1);
    zB0=ffma2(wc.x,ciB[4],zB0); zB1=ffma2(wc.y,ciB[5],zB1);
    zB0=ffma2(wd.x,ciB[6],zB0); zB1=ffma2(wd.y,ciB[7],zB1);
    zB0=ffma2(w8,  ciB[8],zB0);
    float2 ta0=upk2(zA0), ta1=upk2(zA1), tb0=upk2(zB0), tb1=upk2(zB1);
    float zA = bias + ((ta0.x+ta1.x)+(ta0.y+ta1.y));
    float zB = bias + ((tb0.x+tb1.x)+(tb0.y+tb1.y));
    float c1A = fmaxf(zA, 0.0f);
    float c1B = fmaxf(zB, 0.0f);
    const u64 cAp = pk2(c1A,c1A), cBp = pk2(c1B,c1B);
    const ulonglong2* wt = (const ulonglong2*)(cCW2T + j*64);
    #pragma unroll
    for (int q = 0; q < 16; ++q){
      ulonglong2 wv = wt[q];
      h2A[2*q]   = ffma2(wv.x, cAp, h2A[2*q]);
      h2A[2*q+1] = ffma2(wv.y, cAp, h2A[2*q+1]);
      h2B[2*q]   = ffma2(wv.x, cBp, h2B[2*q]);
      h2B[2*q+1] = ffma2(wv.y, cBp, h2B[2*q+1]);
    }
  }
  // relu in place
  #pragma unroll
  for (int j = 0; j < 32; ++j){
    float2 ta = upk2(h2A[j]); h2A[j] = pk2(fmaxf(ta.x,0.0f), fmaxf(ta.y,0.0f));
    float2 tb = upk2(h2B[j]); h2B[j] = pk2(fmaxf(tb.x,0.0f), fmaxf(tb.y,0.0f));
  }

  float rgbA[3], rgbB[3];
  #pragma unroll 1
  for (int c = 0; c < 3; ++c){
    const ulonglong2* w = (const ulonglong2*)(cCW3 + c*64);
    u64 aA0=0ull,aA1=0ull,aB0=0ull,aB1=0ull;
    #pragma unroll
    for (int q = 0; q < 16; ++q){
      ulonglong2 wv = w[q];
      aA0 = ffma2(wv.x, h2A[2*q],   aA0);
      aA1 = ffma2(wv.y, h2A[2*q+1], aA1);
      aB0 = ffma2(wv.x, h2B[2*q],   aB0);
      aB1 = ffma2(wv.y, h2B[2*q+1], aB1);
    }
    float bias = sm[OFF_CB3+c];
    float2 ta0=upk2(aA0), ta1=upk2(aA1), tb0=upk2(aB0), tb1=upk2(aB1);
    rgbA[c] = 1.0f / (1.0f + __expf(-(bias + ((ta0.x+ta1.x)+(ta0.y+ta1.y)))));
    rgbB[c] = 1.0f / (1.0f + __expf(-(bias + ((tb0.x+tb1.x)+(tb0.y+tb1.y)))));
  }

  // ---- sigma (Laplace CDF) + stores ----
  const float bet = 0.015f + fabsf(beta_p[0]);
  {
    const float s = sdfA;
    const float sgn = (s > 0.0f) ? 1.0f : ((s < 0.0f) ? -1.0f : 0.0f);
    float sigma = (0.5f + 0.5f*sgn*expm1f(-fabsf(s)/bet)) / bet;
    if (!(gA.ax && gA.ay && gA.az)) sigma = 0.0f;
    g_srgb[pA] = make_float4(sigma, rgbA[0], rgbA[1], rgbA[2]);
    g_nrm[pA]  = make_float4(nxA, nyA, nzA, 0.0f);
  }
  {
    const float s = sdfB;
    const float sgn = (s > 0.0f) ? 1.0f : ((s < 0.0f) ? -1.0f : 0.0f);
    float sigma = (0.5f + 0.5f*sgn*expm1f(-fabsf(s)/bet)) / bet;
    if (!(gB.ax && gB.ay && gB.az)) sigma = 0.0f;
    g_srgb[pB] = make_float4(sigma, rgbB[0], rgbB[1], rgbB[2]);
    g_nrm[pB]  = make_float4(nxB, nyB, nzB, 0.0f);
  }
}

// ---- per-ray compositing: one warp per ray, 2 samples per lane ----
__global__ void __launch_bounds__(256)
k_render(const float* __restrict__ rdn,
         const unsigned* __restrict__ near_p, const unsigned* __restrict__ far_p,
         float* __restrict__ out)
{
  const int gt = blockIdx.x*256 + threadIdx.x;
  const int r = gt >> 5;
  const int lane = gt & 31;
  if (r >= RR) return;

  const float nearf = decode_scalar(near_p);
  const float farf  = decode_scalar(far_p);
  const float span  = farf - nearf;
  const float dt    = span * (1.0f/64.0f);

  const int p0 = r*64 + lane, p1 = p0 + 32;
  float4 a0 = g_srgb[p0], a1 = g_srgb[p1];
  float4 n0 = g_nrm[p0],  n1 = g_nrm[p1];
  const float dd0 = a0.x * dt;
  const float dd1 = a1.x * dt;

  float cs0 = dd0;
  #pragma unroll
  for (int o = 1; o < 32; o <<= 1){ float v = __shfl_up_sync(0xffffffffu, cs0, o); if (lane >= o) cs0 += v; }
  const float tot0 = __shfl_sync(0xffffffffu, cs0, 31);
  float cs1 = dd1;
  #pragma unroll
  for (int o = 1; o < 32; o <<= 1){ float v = __shfl_up_sync(0xffffffffu, cs1, o); if (lane >= o) cs1 += v; }
  cs1 += tot0;

  const float T0 = __expf(dd0 - cs0);
  const float T1 = __expf(dd1 - cs1);
  const float w0 = (1.0f - __expf(-dd0)) * T0;
  const float w1 = (1.0f - __expf(-dd1)) * T1;
  const float tm0 = nearf + span * (((float)lane + 0.5f)  * (1.0f/64.0f));
  const float tm1 = nearf + span * (((float)lane + 32.5f) * (1.0f/64.0f));

  float v0 = w0*a0.y + w1*a1.y;
  float v1 = w0*a0.z + w1*a1.z;
  float v2 = w0*a0.w + w1*a1.w;
  float v3 = w0*tm0  + w1*tm1;
  float v4 = w0*n0.x + w1*n1.x;
  float v5 = w0*n0.y + w1*n1.y;
  float v6 = w0*n0.z + w1*n1.z;
  float v7 = w0 + w1;

  #pragma unroll
  for (int o = 16; o > 0; o >>= 1){
    v0 += __shfl_down_sync(0xffffffffu, v0, o);
    v1 += __shfl_down_sync(0xffffffffu, v1, o);
    v2 += __shfl_down_sync(0xffffffffu, v2, o);
    v3 += __shfl_down_sync(0xffffffffu, v3, o);
    v4 += __shfl_down_sync(0xffffffffu, v4, o);
    v5 += __shfl_down_sync(0xffffffffu, v5, o);
    v6 += __shfl_down_sync(0xffffffffu, v6, o);
    v7 += __shfl_down_sync(0xffffffffu, v7, o);
  }
  if (lane == 0){
    float* op = out + r*8;
    op[0]=v0; op[1]=v1; op[2]=v2;
    op[3]=v3 / rdn[r];
    op[4]=v4; op[5]=v5; op[6]=v6; op[7]=v7;
  }
}

extern "C" void kernel_launch(void* const* d_in, const int* in_sizes, int n_in,
                              void* d_out, int out_size)
{
  const float* rays_o = (const float*)d_in[0];
  const float* rays_d = (const float*)d_in[1];
  const float* rdn    = (const float*)d_in[2];
  const float* grid   = (const float*)d_in[3];
  const float* sw1 = (const float*)d_in[4];
  const float* sb1 = (const float*)d_in[5];
  const float* sw2 = (const float*)d_in[6];
  const float* sb2 = (const float*)d_in[7];
  const float* sw3 = (const float*)d_in[8];
  const float* sb3 = (const float*)d_in[9];
  const float* cw1 = (const float*)d_in[10];
  const float* cb1 = (const float*)d_in[11];
  const float* cw2 = (const float*)d_in[12];
  const float* cb2 = (const float*)d_in[13];
  const float* cw3 = (const float*)d_in[14];
  const float* cb3 = (const float*)d_in[15];
  const float* beta = (const float*)d_in[16];
  const unsigned* nearp = (const unsigned*)d_in[17];
  const unsigned* farp  = (const unsigned*)d_in[18];

  float* out = (float*)d_out;
  float* out_grads = out + RR*8;   // output = [rendered (R,8), sdf_grads (R*S,3)]

  // Resolve constant-bank addresses (pure address queries; no stream work).
  void *w2t_p = nullptr, *cw2t_p = nullptr, *w3_p = nullptr, *cw3_p = nullptr;
  cudaGetSymbolAddress(&w2t_p,  cW2T);
  cudaGetSymbolAddress(&cw2t_p, cCW2T);
  cudaGetSymbolAddress(&w3_p,   cW3);
  cudaGetSymbolAddress(&cw3_p,  cCW3);

  // 1) prep kernel writes transposed weights straight into the constant bank
  k_prep<<<1, 256>>>(sw2, cw2, sw3, cw3,
                     (float*)w2t_p, (float*)cw2t_p, (float*)w3_p, (float*)cw3_p);

  // 2) main point kernel + compositing
  k_points<<<NPTS/(TPB*PPT), TPB>>>(
      rays_o, rays_d, grid,
      sw1, sb1, sb2, sb3,
      cw1, cb1, cb2, cb3,
      beta, nearp, farp, out_grads);

  k_render<<<(RR*32)/256, 256>>>(rdn, nearp, farp, out);
}

// round 13
// speedup vs baseline: 6.5036x; 1.1953x over previous
#include <cuda_runtime.h>

#define RR 16384
#define SS 64
#define GG 128
#define EE 16
#define NPTS (RR*SS)
#define SX (GG*GG*EE)
#define SY (GG*EE)
#define TPB 128
#define PPT 2            // points per thread

typedef unsigned long long u64;

// ---- scratch (per-point) ----
__device__ float4 g_srgb[NPTS];   // (sigma, r, g, b)
__device__ float4 g_nrm[NPTS];    // (nx, ny, nz, 0)

// Large streaming matrices in the constant bank (uniform-port loads).
__constant__ __align__(16) float cW2T[4096];   // [k][j] = sw2[j][k]
__constant__ __align__(16) float cCW2T[4096];  // [k][j] = cw2[j][k]
__constant__ __align__(16) float cW3[1024];    // 16x64 row-major
__constant__ __align__(16) float cCW3[192];    // 3x64 row-major

// ---- packed f32x2 helpers ----
__device__ __forceinline__ u64 pk2(float a, float b){
  u64 r; asm("mov.b64 %0, {%1,%2};" : "=l"(r) : "f"(a), "f"(b)); return r;
}
__device__ __forceinline__ float2 upk2(u64 v){
  float2 t; asm("mov.b64 {%0,%1}, %2;" : "=f"(t.x), "=f"(t.y) : "l"(v)); return t;
}
__device__ __forceinline__ u64 ffma2(u64 a, u64 b, u64 c){
  u64 r; asm("fma.rn.f32x2 %0, %1, %2, %3;" : "=l"(r) : "l"(a), "l"(b), "l"(c)); return r;
}
__device__ __forceinline__ u64 fmul2(u64 a, u64 b){
  u64 r; asm("mul.rn.f32x2 %0, %1, %2;" : "=l"(r) : "l"(a), "l"(b)); return r;
}

__device__ __forceinline__ float decode_scalar(const unsigned* p){
  unsigned u = *p;
  if (u == 0u) return 0.0f;
  if ((u >> 23) == 0u) return (float)(int)u;   // small integer bit pattern
  return __uint_as_float(u);
}
__device__ __forceinline__ float softplus100(float z){
  float y = 100.0f*z;
  float t = __expf(-fabsf(y));
  return (fmaxf(y,0.0f) + __logf(1.0f + t)) * 0.01f;
}
__device__ __forceinline__ float dact_h(float h){ return 1.0f - __expf(-100.0f*h); }

// ---- shared layout (float offsets; dynamic smem) ----
#define OFF_W1    0      // 1024  (64x16 row-major)
#define OFF_B1    1024   // 64
#define OFF_B2    1088   // 64
#define OFF_B3    1152   // 16
#define OFF_CW1P  1168   // 1536  (64x24, rows zero-padded from 18)
#define OFF_CB1   2704   // 64
#define OFF_CB2   2768   // 64
#define OFF_CB3   2832   // 3
#define OFF_S1    2840   // 64*TPB u64 per-thread scratch (16B aligned)
#define SM_FLOATS (OFF_S1 + 64*TPB*2)
#define SMEM_BYTES (SM_FLOATS*4)

struct Geo {
  float fx, fy, fz;
  int base;
  bool ax, ay, az;
};

// ---- prep: write transposed / raw weights directly into the constant bank ----
__global__ void k_prep(const float* __restrict__ sw2, const float* __restrict__ cw2,
                       const float* __restrict__ sw3, const float* __restrict__ cw3,
                       float* __restrict__ dW2T, float* __restrict__ dCW2T,
                       float* __restrict__ dW3, float* __restrict__ dCW3)
{
  for (int i = threadIdx.x; i < 4096; i += blockDim.x){
    int j = i >> 6, k = i & 63;
    dW2T [k*64 + j] = sw2[i];
    dCW2T[k*64 + j] = cw2[i];
  }
  for (int i = threadIdx.x; i < 1024; i += blockDim.x) dW3[i] = sw3[i];
  for (int i = threadIdx.x; i < 192;  i += blockDim.x) dCW3[i] = cw3[i];
}

__global__ void __launch_bounds__(TPB, 2)
k_points(const float* __restrict__ rays_o, const float* __restrict__ rays_d,
         const float* __restrict__ grid,
         const float* __restrict__ sw1, const float* __restrict__ sb1,
         const float* __restrict__ sb2, const float* __restrict__ sb3,
         const float* __restrict__ cw1, const float* __restrict__ cb1,
         const float* __restrict__ cb2, const float* __restrict__ cb3,
         const float* __restrict__ beta_p,
         const unsigned* __restrict__ near_p, const unsigned* __restrict__ far_p,
         float* __restrict__ out_grads)
{
  extern __shared__ __align__(16) float sm[];
  const int tid = threadIdx.x;

  // ---- cooperative staging of SMALL arrays ----
  for (int i = tid; i < 1024; i += TPB) sm[OFF_W1+i]=sw1[i];
  for (int i = tid; i < 1536; i += TPB) sm[OFF_CW1P+i] = 0.0f;
  if (tid < 64){ sm[OFF_B1+tid]=sb1[tid]; sm[OFF_B2+tid]=sb2[tid];
                 sm[OFF_CB1+tid]=cb1[tid]; sm[OFF_CB2+tid]=cb2[tid]; }
  if (tid < 16) sm[OFF_B3+tid]=sb3[tid];
  if (tid < 3)  sm[OFF_CB3+tid]=cb3[tid];
  __syncthreads();
  for (int i = tid; i < 1152; i += TPB){
    int j = i / 18, c = i - j*18;
    sm[OFF_CW1P + j*24 + c] = cw1[i];
  }
  __syncthreads();

  u64* s1p = ((u64*)(sm + OFF_S1)) + tid;   // per-thread scratch, stride TPB per k

  const int pA = blockIdx.x*(TPB*PPT) + tid;
  const int pB = pA + TPB;

  const float nearf = decode_scalar(near_p);
  const float farf  = decode_scalar(far_p);
  const float span  = farf - nearf;

  // ---- geometry + forward gather (packed embeddings: 8 pairs per point) ----
  Geo gA, gB;
  u64 epA[8], epB[8];

  #pragma unroll
  for (int pi = 0; pi < PPT; ++pi){
    const int p = pi ? pB : pA;
    const int r = p >> 6;
    const int s = p & 63;
    const float tm = nearf + span * ((s + 0.5f) * (1.0f/64.0f));
    const float px = fmaf(tm, rays_d[3*r+0], rays_o[3*r+0]);
    const float py = fmaf(tm, rays_d[3*r+1], rays_o[3*r+1]);
    const float pz = fmaf(tm, rays_d[3*r+2], rays_o[3*r+2]);

    const float HALF = 0.5f*(float)(GG-1);
    float grx = (px*(1.0f/1.3f) + 1.0f)*HALF;
    float gry = (py*(1.0f/1.3f) + 1.0f)*HALF;
    float grz = (pz*(1.0f/1.3f) + 1.0f)*HALF;
    const float GM1 = (float)(GG-1);
    Geo g;
    g.ax = (grx >= 0.0f) && (grx <= GM1);
    g.ay = (gry >= 0.0f) && (gry <= GM1);
    g.az = (grz >= 0.0f) && (grz <= GM1);
    float gcx = fminf(fmaxf(grx,0.0f), GM1);
    float gcy = fminf(fmaxf(gry,0.0f), GM1);
    float gcz = fminf(fmaxf(grz,0.0f), GM1);
    int ix = min((int)gcx, GG-2);
    int iy = min((int)gcy, GG-2);
    int iz = min((int)gcz, GG-2);
    g.fx = gcx - (float)ix;
    g.fy = gcy - (float)iy;
    g.fz = gcz - (float)iz;
    g.base = ((ix*GG + iy)*GG + iz)*EE;

    u64 ep[8];
    #pragma unroll
    for (int i = 0; i < 8; ++i) ep[i] = 0ull;
    #pragma unroll
    for (int dx = 0; dx < 2; ++dx){
      const float wxv = dx ? g.fx : (1.0f - g.fx);
      #pragma unroll
      for (int dy = 0; dy < 2; ++dy){
        const float wyv = dy ? g.fy : (1.0f - g.fy);
        const ulonglong2* gp = (const ulonglong2*)(grid + g.base + dx*SX + dy*SY);
        const float w0 = wxv*wyv*(1.0f - g.fz);
        const float w1 = wxv*wyv*g.fz;
        const u64 w0p = pk2(w0,w0), w1p = pk2(w1,w1);
        #pragma unroll
        for (int i = 0; i < 4; ++i){
          ulonglong2 a = gp[i];
          ep[2*i]   = ffma2(w0p, a.x, ep[2*i]);
          ep[2*i+1] = ffma2(w0p, a.y, ep[2*i+1]);
        }
        #pragma unroll
        for (int i = 0; i < 4; ++i){
          ulonglong2 b = gp[4+i];
          ep[2*i]   = ffma2(w1p, b.x, ep[2*i]);
          ep[2*i+1] = ffma2(w1p, b.y, ep[2*i+1]);
        }
      }
    }
    if (pi){ gB=g;
      #pragma unroll
      for (int i=0;i<8;++i) epB[i]=ep[i];
    } else { gA=g;
      #pragma unroll
      for (int i=0;i<8;++i) epA[i]=ep[i];
    }
  }

  // ---- SDF layers 1+2 fused: h2 accumulators packed (32 pairs per point) ----
  u64 h2A[32], h2B[32];
  #pragma unroll
  for (int j = 0; j < 32; ++j){
    u64 b = ((const u64*)(sm + OFF_B2))[j];
    h2A[j]=b; h2B[j]=b;
  }

  #pragma unroll 2
  for (int k = 0; k < 64; ++k){
    const ulonglong2* w1p = (const ulonglong2*)(sm + OFF_W1 + k*16);
    ulonglong2 wa=w1p[0], wb=w1p[1], wc=w1p[2], wd=w1p[3];
    const float b1 = sm[OFF_B1+k];
    u64 zA0=0ull, zA1=0ull, zB0=0ull, zB1=0ull;
    zA0=ffma2(wa.x,epA[0],zA0); zA1=ffma2(wa.y,epA[1],zA1);
    zA0=ffma2(wb.x,epA[2],zA0); zA1=ffma2(wb.y,epA[3],zA1);
    zA0=ffma2(wc.x,epA[4],zA0); zA1=ffma2(wc.y,epA[5],zA1);
    zA0=ffma2(wd.x,epA[6],zA0); zA1=ffma2(wd.y,epA[7],zA1);
    zB0=ffma2(wa.x,epB[0],zB0); zB1=ffma2(wa.y,epB[1],zB1);
    zB0=ffma2(wb.x,epB[2],zB0); zB1=ffma2(wb.y,epB[3],zB1);
    zB0=ffma2(wc.x,epB[4],zB0); zB1=ffma2(wc.y,epB[5],zB1);
    zB0=ffma2(wd.x,epB[6],zB0); zB1=ffma2(wd.y,epB[7],zB1);
    float2 a0=upk2(zA0), a1=upk2(zA1), b0=upk2(zB0), b1v=upk2(zB1);
    float zA = b1 + ((a0.x+a1.x)+(a0.y+a1.y));
    float zB = b1 + ((b0.x+b1v.x)+(b0.y+b1v.y));
    float hA = softplus100(zA);
    float hB = softplus100(zB);
    // stash sigmoid(100 z1) for the backward pass (per-thread scratch, no sync)
    s1p[k*TPB] = pk2(dact_h(hA), dact_h(hB));
    const u64 hAp = pk2(hA,hA), hBp = pk2(hB,hB);
    const ulonglong2* w2p = (const ulonglong2*)(cW2T + k*64);
    #pragma unroll
    for (int q = 0; q < 16; ++q){
      ulonglong2 wv = w2p[q];
      h2A[2*q]   = ffma2(wv.x, hAp, h2A[2*q]);
      h2A[2*q+1] = ffma2(wv.y, hAp, h2A[2*q+1]);
      h2B[2*q]   = ffma2(wv.x, hBp, h2B[2*q]);
      h2B[2*q+1] = ffma2(wv.y, hBp, h2B[2*q+1]);
    }
  }
  // activation in place
  #pragma unroll
  for (int j = 0; j < 32; ++j){
    float2 ta = upk2(h2A[j]); h2A[j] = pk2(softplus100(ta.x), softplus100(ta.y));
    float2 tb = upk2(h2B[j]); h2B[j] = pk2(softplus100(tb.x), softplus100(tb.y));
  }

  // ---- layer 3 (16 outputs, W3 const) ----
  float sdfA, sdfB;
  float featA[15], featB[15];
  #pragma unroll 1
  for (int c = 0; c < 16; ++c){
    const ulonglong2* w = (const ulonglong2*)(cW3 + c*64);
    u64 aA0=0ull,aA1=0ull,aB0=0ull,aB1=0ull;
    #pragma unroll
    for (int q = 0; q < 16; ++q){
      ulonglong2 wv = w[q];
      aA0 = ffma2(wv.x, h2A[2*q],   aA0);
      aA1 = ffma2(wv.y, h2A[2*q+1], aA1);
      aB0 = ffma2(wv.x, h2B[2*q],   aB0);
      aB1 = ffma2(wv.y, h2B[2*q+1], aB1);
    }
    float bias = sm[OFF_B3+c];
    float2 ta0=upk2(aA0), ta1=upk2(aA1), tb0=upk2(aB0), tb1=upk2(aB1);
    float zA = bias + ((ta0.x+ta1.x)+(ta0.y+ta1.y));
    float zB = bias + ((tb0.x+tb1.x)+(tb0.y+tb1.y));
    if (c == 0){ sdfA = zA; sdfB = zB; }
    else { featA[c-1] = zA; featB[c-1] = zB; }
  }

  // ---- backward: g2 = W3[0][:] * sigmoid(100 z2), overwrite h2 (packed) ----
  #pragma unroll
  for (int j = 0; j < 32; ++j){
    u64 w3p = ((const u64*)cW3)[j];
    float2 ta = upk2(h2A[j]);
    float2 tb = upk2(h2B[j]);
    h2A[j] = fmul2(w3p, pk2(dact_h(ta.x), dact_h(ta.y)));
    h2B[j] = fmul2(w3p, pk2(dact_h(tb.x), dact_h(tb.y)));
  }

  u64 deA[8], deB[8];
  #pragma unroll
  for (int i = 0; i < 8; ++i){ deA[i]=0ull; deB[i]=0ull; }

  #pragma unroll 2
  for (int k = 0; k < 64; ++k){
    const ulonglong2* w2p = (const ulonglong2*)(cW2T + k*64);
    u64 aA0=0ull,aA1=0ull,aB0=0ull,aB1=0ull;
    #pragma unroll
    for (int q = 0; q < 16; ++q){
      ulonglong2 wv = w2p[q];
      aA0 = ffma2(wv.x, h2A[2*q],   aA0);
      aA1 = ffma2(wv.y, h2A[2*q+1], aA1);
      aB0 = ffma2(wv.x, h2B[2*q],   aB0);
      aB1 = ffma2(wv.y, h2B[2*q+1], aB1);
    }
    float2 ta0=upk2(aA0), ta1=upk2(aA1), tb0=upk2(aB0), tb1=upk2(aB1);
    float sumA = (ta0.x+ta1.x)+(ta0.y+ta1.y);
    float sumB = (tb0.x+tb1.x)+(tb0.y+tb1.y);

    // load stored sigmoid(100 z1) instead of recomputing the preactivation
    float2 sv = upk2(s1p[k*TPB]);
    const float dzA = sumA * sv.x;
    const float dzB = sumB * sv.y;

    const ulonglong2* w1p = (const ulonglong2*)(sm + OFF_W1 + k*16);
    ulonglong2 wa=w1p[0], wb=w1p[1], wc=w1p[2], wd=w1p[3];
    const u64 dzAp = pk2(dzA,dzA), dzBp = pk2(dzB,dzB);
    deA[0]=ffma2(dzAp,wa.x,deA[0]); deA[1]=ffma2(dzAp,wa.y,deA[1]);
    deA[2]=ffma2(dzAp,wb.x,deA[2]); deA[3]=ffma2(dzAp,wb.y,deA[3]);
    deA[4]=ffma2(dzAp,wc.x,deA[4]); deA[5]=ffma2(dzAp,wc.y,deA[5]);
    deA[6]=ffma2(dzAp,wd.x,deA[6]); deA[7]=ffma2(dzAp,wd.y,deA[7]);
    deB[0]=ffma2(dzBp,wa.x,deB[0]); deB[1]=ffma2(dzBp,wa.y,deB[1]);
    deB[2]=ffma2(dzBp,wb.x,deB[2]); deB[3]=ffma2(dzBp,wb.y,deB[3]);
    deB[4]=ffma2(dzBp,wc.x,deB[4]); deB[5]=ffma2(dzBp,wc.y,deB[5]);
    deB[6]=ffma2(dzBp,wd.x,deB[6]); deB[7]=ffma2(dzBp,wd.y,deB[7]);
  }

  // ---- re-gather corners (packed dot) -> spatial gradient; normals ----
  float nxA,nyA,nzA, nxB,nyB,nzB;
  #pragma unroll
  for (int pi = 0; pi < PPT; ++pi){
    const Geo g = pi ? gB : gA;
    const u64* de = pi ? deB : deA;
    float gx=0.f, gy=0.f, gz=0.f;
    #pragma unroll
    for (int dx = 0; dx < 2; ++dx){
      const float wxv = dx ? g.fx : (1.0f - g.fx);
      #pragma unroll
      for (int dy = 0; dy < 2; ++dy){
        const float wyv = dy ? g.fy : (1.0f - g.fy);
        const ulonglong2* gp = (const ulonglong2*)(grid + g.base + dx*SX + dy*SY);
        u64 acc0=0ull, acc1=0ull;
        #pragma unroll
        for (int i = 0; i < 4; ++i){
          ulonglong2 a = gp[i];
          acc0 = ffma2(a.x, de[2*i],   acc0);
          acc0 = ffma2(a.y, de[2*i+1], acc0);
        }
        #pragma unroll
        for (int i = 0; i < 4; ++i){
          ulonglong2 b = gp[4+i];
          acc1 = ffma2(b.x, de[2*i],   acc1);
          acc1 = ffma2(b.y, de[2*i+1], acc1);
        }
        float2 t0 = upk2(acc0), t1 = upk2(acc1);
        float sA = t0.x + t0.y;
        float sB = t1.x + t1.y;
        float sc = fmaf(g.fz, sB - sA, sA);
        gz = fmaf(wxv*wyv, sB - sA, gz);
        gx += dx ? wyv*sc : -wyv*sc;
        gy += dy ? wxv*sc : -wxv*sc;
      }
    }
    const float SCALE = 0.5f*(float)(GG-1)/1.3f;
    const float Gx = g.ax ? gx*SCALE : 0.0f;
    const float Gy = g.ay ? gy*SCALE : 0.0f;
    const float Gz = g.az ? gz*SCALE : 0.0f;
    const int p = pi ? pB : pA;
    out_grads[3*p+0] = Gx;
    out_grads[3*p+1] = Gy;
    out_grads[3*p+2] = Gz;
    const float nn = sqrtf(Gx*Gx + Gy*Gy + Gz*Gz);
    const float inv = 1.0f / fmaxf(nn, 1e-12f);
    if (pi){ nxB=Gx*inv; nyB=Gy*inv; nzB=Gz*inv; }
    else   { nxA=Gx*inv; nyA=Gy*inv; nzA=Gz*inv; }
  }

  // ---- color MLP (packed): cin as 9 pairs; reuse h2 as c2 accumulators ----
  u64 ciA[9], ciB[9];
  #pragma unroll
  for (int i = 0; i < 7; ++i){
    ciA[i] = pk2(featA[2*i], featA[2*i+1]);
    ciB[i] = pk2(featB[2*i], featB[2*i+1]);
  }
  ciA[7] = pk2(featA[14], nxA); ciA[8] = pk2(nyA, nzA);
  ciB[7] = pk2(featB[14], nxB); ciB[8] = pk2(nyB, nzB);

  #pragma unroll
  for (int j = 0; j < 32; ++j){
    u64 b = ((const u64*)(sm + OFF_CB2))[j];
    h2A[j]=b; h2B[j]=b;
  }

  #pragma unroll 1
  for (int j = 0; j < 64; ++j){
    const ulonglong2* w = (const ulonglong2*)(sm + OFF_CW1P + j*24);
    ulonglong2 wa=w[0], wb=w[1], wc=w[2], wd=w[3];
    u64 w8 = ((const u64*)(sm + OFF_CW1P + j*24))[8];
    const float bias = sm[OFF_CB1+j];
    u64 zA0=0ull, zA1=0ull, zB0=0ull, zB1=0ull;
    zA0=ffma2(wa.x,ciA[0],zA0); zA1=ffma2(wa.y,ciA[1],zA1);
    zA0=ffma2(wb.x,ciA[2],zA0); zA1=ffma2(wb.y,ciA[3],zA1);
    zA0=ffma2(wc.x,ciA[4],zA0); zA1=ffma2(wc.y,ciA[5],zA1);
    zA0=ffma2(wd.x,ciA[6],zA0); zA1=ffma2(wd.y,ciA[7],zA1);
    zA0=ffma2(w8,  ciA[8],zA0);
    zB0=ffma2(wa.x,ciB[0],zB0); zB1=ffma2(wa.y,ciB[1],zB1);
    zB0=ffma2(wb.x,ciB[2],zB0); zB1=ffma2(wb.y,ciB[3],zB1);
    zB0=ffma2(wc.x,ciB[4],zB0); zB1=ffma2(wc.y,ciB[5],zB1);
    zB0=ffma2(wd.x,ciB[6],zB0); zB1=ffma2(wd.y,ciB[7],zB1);
    zB0=ffma2(w8,  ciB[8],zB0);
    float2 ta0=upk2(zA0), ta1=upk2(zA1), tb0=upk2(zB0), tb1=upk2(zB1);
    float zA = bias + ((ta0.x+ta1.x)+(ta0.y+ta1.y));
    float zB = bias + ((tb0.x+tb1.x)+(tb0.y+tb1.y));
    float c1A = fmaxf(zA, 0.0f);
    float c1B = fmaxf(zB, 0.0f);
    const u64 cAp = pk2(c1A,c1A), cBp = pk2(c1B,c1B);
    const ulonglong2* wt = (const ulonglong2*)(cCW2T + j*64);
    #pragma unroll
    for (int q = 0; q < 16; ++q){
      ulonglong2 wv = wt[q];
      h2A[2*q]   = ffma2(wv.x, cAp, h2A[2*q]);
      h2A[2*q+1] = ffma2(wv.y, cAp, h2A[2*q+1]);
      h2B[2*q]   = ffma2(wv.x, cBp, h2B[2*q]);
      h2B[2*q+1] = ffma2(wv.y, cBp, h2B[2*q+1]);
    }
  }
  // relu in place
  #pragma unroll
  for (int j = 0; j < 32; ++j){
    float2 ta = upk2(h2A[j]); h2A[j] = pk2(fmaxf(ta.x,0.0f), fmaxf(ta.y,0.0f));
    float2 tb = upk2(h2B[j]); h2B[j] = pk2(fmaxf(tb.x,0.0f), fmaxf(tb.y,0.0f));
  }

  float rgbA[3], rgbB[3];
  #pragma unroll 1
  for (int c = 0; c < 3; ++c){
    const ulonglong2* w = (const ulonglong2*)(cCW3 + c*64);
    u64 aA0=0ull,aA1=0ull,aB0=0ull,aB1=0ull;
    #pragma unroll
    for (int q = 0; q < 16; ++q){
      ulonglong2 wv = w[q];
      aA0 = ffma2(wv.x, h2A[2*q],   aA0);
      aA1 = ffma2(wv.y, h2A[2*q+1], aA1);
      aB0 = ffma2(wv.x, h2B[2*q],   aB0);
      aB1 = ffma2(wv.y, h2B[2*q+1], aB1);
    }
    float bias = sm[OFF_CB3+c];
    float2 ta0=upk2(aA0), ta1=upk2(aA1), tb0=upk2(aB0), tb1=upk2(aB1);
    rgbA[c] = 1.0f / (1.0f + __expf(-(bias + ((ta0.x+ta1.x)+(ta0.y+ta1.y)))));
    rgbB[c] = 1.0f / (1.0f + __expf(-(bias + ((tb0.x+tb1.x)+(tb0.y+tb1.y)))));
  }

  // ---- sigma (Laplace CDF) + stores ----
  const float bet = 0.015f + fabsf(beta_p[0]);
  {
    const float s = sdfA;
    const float sgn = (s > 0.0f) ? 1.0f : ((s < 0.0f) ? -1.0f : 0.0f);
    float sigma = (0.5f + 0.5f*sgn*expm1f(-fabsf(s)/bet)) / bet;
    if (!(gA.ax && gA.ay && gA.az)) sigma = 0.0f;
    g_srgb[pA] = make_float4(sigma, rgbA[0], rgbA[1], rgbA[2]);
    g_nrm[pA]  = make_float4(nxA, nyA, nzA, 0.0f);
  }
  {
    const float s = sdfB;
    const float sgn = (s > 0.0f) ? 1.0f : ((s < 0.0f) ? -1.0f : 0.0f);
    float sigma = (0.5f + 0.5f*sgn*expm1f(-fabsf(s)/bet)) / bet;
    if (!(gB.ax && gB.ay && gB.az)) sigma = 0.0f;
    g_srgb[pB] = make_float4(sigma, rgbB[0], rgbB[1], rgbB[2]);
    g_nrm[pB]  = make_float4(nxB, nyB, nzB, 0.0f);
  }
}

// ---- per-ray compositing: one warp per ray, 2 samples per lane ----
__global__ void __launch_bounds__(256)
k_render(const float* __restrict__ rdn,
         const unsigned* __restrict__ near_p, const unsigned* __restrict__ far_p,
         float* __restrict__ out)
{
  const int gt = blockIdx.x*256 + threadIdx.x;
  const int r = gt >> 5;
  const int lane = gt & 31;
  if (r >= RR) return;

  const float nearf = decode_scalar(near_p);
  const float farf  = decode_scalar(far_p);
  const float span  = farf - nearf;
  const float dt    = span * (1.0f/64.0f);

  const int p0 = r*64 + lane, p1 = p0 + 32;
  float4 a0 = g_srgb[p0], a1 = g_srgb[p1];
  float4 n0 = g_nrm[p0],  n1 = g_nrm[p1];
  const float dd0 = a0.x * dt;
  const float dd1 = a1.x * dt;

  float cs0 = dd0;
  #pragma unroll
  for (int o = 1; o < 32; o <<= 1){ float v = __shfl_up_sync(0xffffffffu, cs0, o); if (lane >= o) cs0 += v; }
  const float tot0 = __shfl_sync(0xffffffffu, cs0, 31);
  float cs1 = dd1;
  #pragma unroll
  for (int o = 1; o < 32; o <<= 1){ float v = __shfl_up_sync(0xffffffffu, cs1, o); if (lane >= o) cs1 += v; }
  cs1 += tot0;

  const float T0 = __expf(dd0 - cs0);
  const float T1 = __expf(dd1 - cs1);
  const float w0 = (1.0f - __expf(-dd0)) * T0;
  const float w1 = (1.0f - __expf(-dd1)) * T1;
  const float tm0 = nearf + span * (((float)lane + 0.5f)  * (1.0f/64.0f));
  const float tm1 = nearf + span * (((float)lane + 32.5f) * (1.0f/64.0f));

  float v0 = w0*a0.y + w1*a1.y;
  float v1 = w0*a0.z + w1*a1.z;
  float v2 = w0*a0.w + w1*a1.w;
  float v3 = w0*tm0  + w1*tm1;
  float v4 = w0*n0.x + w1*n1.x;
  float v5 = w0*n0.y + w1*n1.y;
  float v6 = w0*n0.z + w1*n1.z;
  float v7 = w0 + w1;

  #pragma unroll
  for (int o = 16; o > 0; o >>= 1){
    v0 += __shfl_down_sync(0xffffffffu, v0, o);
    v1 += __shfl_down_sync(0xffffffffu, v1, o);
    v2 += __shfl_down_sync(0xffffffffu, v2, o);
    v3 += __shfl_down_sync(0xffffffffu, v3, o);
    v4 += __shfl_down_sync(0xffffffffu, v4, o);
    v5 += __shfl_down_sync(0xffffffffu, v5, o);
    v6 += __shfl_down_sync(0xffffffffu, v6, o);
    v7 += __shfl_down_sync(0xffffffffu, v7, o);
  }
  if (lane == 0){
    float* op = out + r*8;
    op[0]=v0; op[1]=v1; op[2]=v2;
    op[3]=v3 / rdn[r];
    op[4]=v4; op[5]=v5; op[6]=v6; op[7]=v7;
  }
}

extern "C" void kernel_launch(void* const* d_in, const int* in_sizes, int n_in,
                              void* d_out, int out_size)
{
  const float* rays_o = (const float*)d_in[0];
  const float* rays_d = (const float*)d_in[1];
  const float* rdn    = (const float*)d_in[2];
  const float* grid   = (const float*)d_in[3];
  const float* sw1 = (const float*)d_in[4];
  const float* sb1 = (const float*)d_in[5];
  const float* sw2 = (const float*)d_in[6];
  const float* sb2 = (const float*)d_in[7];
  const float* sw3 = (const float*)d_in[8];
  const float* sb3 = (const float*)d_in[9];
  const float* cw1 = (const float*)d_in[10];
  const float* cb1 = (const float*)d_in[11];
  const float* cw2 = (const float*)d_in[12];
  const float* cb2 = (const float*)d_in[13];
  const float* cw3 = (const float*)d_in[14];
  const float* cb3 = (const float*)d_in[15];
  const float* beta = (const float*)d_in[16];
  const unsigned* nearp = (const unsigned*)d_in[17];
  const unsigned* farp  = (const unsigned*)d_in[18];

  float* out = (float*)d_out;
  float* out_grads = out + RR*8;   // output = [rendered (R,8), sdf_grads (R*S,3)]

  // Resolve constant-bank addresses (pure address queries; no stream work).
  void *w2t_p = nullptr, *cw2t_p = nullptr, *w3_p = nullptr, *cw3_p = nullptr;
  cudaGetSymbolAddress(&w2t_p,  cW2T);
  cudaGetSymbolAddress(&cw2t_p, cCW2T);
  cudaGetSymbolAddress(&w3_p,   cW3);
  cudaGetSymbolAddress(&cw3_p,  cCW3);

  cudaFuncSetAttribute(k_points, cudaFuncAttributeMaxDynamicSharedMemorySize, SMEM_BYTES);

  // 1) prep kernel writes transposed weights straight into the constant bank
  k_prep<<<1, 256>>>(sw2, cw2, sw3, cw3,
                     (float*)w2t_p, (float*)cw2t_p, (float*)w3_p, (float*)cw3_p);

  // 2) main point kernel + compositing
  k_points<<<NPTS/(TPB*PPT), TPB, SMEM_BYTES>>>(
      rays_o, rays_d, grid,
      sw1, sb1, sb2, sb3,
      cw1, cb1, cb2, cb3,
      beta, nearp, farp, out_grads);

  k_render<<<(RR*32)/256, 256>>>(rdn, nearp, farp, out);
}

// round 14
// speedup vs baseline: 6.9311x; 1.0657x over previous
#include <cuda_runtime.h>

#define RR 16384
#define SS 64
#define GG 128
#define EE 16
#define NPTS (RR*SS)
#define SX (GG*GG*EE)
#define SY (GG*EE)
#define TPB 128
#define PPT 2            // points per thread (A = s0-31, B = s32-63 of the SAME ray)

typedef unsigned long long u64;

// ---- scratch (per-point) ----
__device__ float4 g_srgb[NPTS];   // (sigma, r, g, b)
__device__ float4 g_nrm[NPTS];    // (nx, ny, nz, 0)

// Large streaming matrices in the constant bank (uniform-port loads).
__constant__ __align__(16) float cW2T[4096];   // [k][j] = sw2[j][k]
__constant__ __align__(16) float cCW2T[4096];  // [k][j] = cw2[j][k]
__constant__ __align__(16) float cW3[1024];    // 16x64 row-major
__constant__ __align__(16) float cCW3[192];    // 3x64 row-major

// ---- packed f32x2 helpers ----
__device__ __forceinline__ u64 pk2(float a, float b){
  u64 r; asm("mov.b64 %0, {%1,%2};" : "=l"(r) : "f"(a), "f"(b)); return r;
}
__device__ __forceinline__ float2 upk2(u64 v){
  float2 t; asm("mov.b64 {%0,%1}, %2;" : "=f"(t.x), "=f"(t.y) : "l"(v)); return t;
}
__device__ __forceinline__ u64 ffma2(u64 a, u64 b, u64 c){
  u64 r; asm("fma.rn.f32x2 %0, %1, %2, %3;" : "=l"(r) : "l"(a), "l"(b), "l"(c)); return r;
}
__device__ __forceinline__ u64 fmul2(u64 a, u64 b){
  u64 r; asm("mul.rn.f32x2 %0, %1, %2;" : "=l"(r) : "l"(a), "l"(b)); return r;
}

__device__ __forceinline__ float decode_scalar(const unsigned* p){
  unsigned u = *p;
  if (u == 0u) return 0.0f;
  if ((u >> 23) == 0u) return (float)(int)u;   // small integer bit pattern
  return __uint_as_float(u);
}
__device__ __forceinline__ float softplus100(float z){
  float y = 100.0f*z;
  float t = __expf(-fabsf(y));
  return (fmaxf(y,0.0f) + __logf(1.0f + t)) * 0.01f;
}
__device__ __forceinline__ float dact_h(float h){ return 1.0f - __expf(-100.0f*h); }

// ---- shared layout (float offsets; dynamic smem) ----
#define OFF_W1    0      // 1024  (64x16 row-major)
#define OFF_B1    1024   // 64
#define OFF_B2    1088   // 64
#define OFF_B3    1152   // 16
#define OFF_CW1P  1168   // 1536  (64x24, rows zero-padded from 18)
#define OFF_CB1   2704   // 64
#define OFF_CB2   2768   // 64
#define OFF_CB3   2832   // 3
#define OFF_S1    2840   // 64*TPB u64 per-thread scratch (16B aligned)
#define SM_FLOATS (OFF_S1 + 64*TPB*2)
#define SMEM_BYTES (SM_FLOATS*4)

struct Geo {
  float fx, fy, fz;
  int base;
  bool ax, ay, az;
};

// ---- prep: write transposed / raw weights directly into the constant bank ----
__global__ void k_prep(const float* __restrict__ sw2, const float* __restrict__ cw2,
                       const float* __restrict__ sw3, const float* __restrict__ cw3,
                       float* __restrict__ dW2T, float* __restrict__ dCW2T,
                       float* __restrict__ dW3, float* __restrict__ dCW3)
{
  for (int i = threadIdx.x; i < 4096; i += blockDim.x){
    int j = i >> 6, k = i & 63;
    dW2T [k*64 + j] = sw2[i];
    dCW2T[k*64 + j] = cw2[i];
  }
  for (int i = threadIdx.x; i < 1024; i += blockDim.x) dW3[i] = sw3[i];
  for (int i = threadIdx.x; i < 192;  i += blockDim.x) dCW3[i] = cw3[i];
}

// ---- single-point color MLP (used when the partner point is fully masked) ----
__device__ __forceinline__ void color_single(const float* sm, const u64* ci,
                                             u64* acc /*32*/, float* rgb)
{
  #pragma unroll
  for (int j = 0; j < 32; ++j) acc[j] = ((const u64*)(sm + OFF_CB2))[j];

  #pragma unroll 1
  for (int j = 0; j < 64; ++j){
    const ulonglong2* w = (const ulonglong2*)(sm + OFF_CW1P + j*24);
    ulonglong2 wa=w[0], wb=w[1], wc=w[2], wd=w[3];
    u64 w8 = ((const u64*)(sm + OFF_CW1P + j*24))[8];
    const float bias = sm[OFF_CB1+j];
    u64 z0=0ull, z1=0ull;
    z0=ffma2(wa.x,ci[0],z0); z1=ffma2(wa.y,ci[1],z1);
    z0=ffma2(wb.x,ci[2],z0); z1=ffma2(wb.y,ci[3],z1);
    z0=ffma2(wc.x,ci[4],z0); z1=ffma2(wc.y,ci[5],z1);
    z0=ffma2(wd.x,ci[6],z0); z1=ffma2(wd.y,ci[7],z1);
    z0=ffma2(w8,  ci[8],z0);
    float2 t0=upk2(z0), t1=upk2(z1);
    float z = bias + ((t0.x+t1.x)+(t0.y+t1.y));
    float c1 = fmaxf(z, 0.0f);
    const u64 cp = pk2(c1,c1);
    const ulonglong2* wt = (const ulonglong2*)(cCW2T + j*64);
    #pragma unroll
    for (int q = 0; q < 16; ++q){
      ulonglong2 wv = wt[q];
      acc[2*q]   = ffma2(wv.x, cp, acc[2*q]);
      acc[2*q+1] = ffma2(wv.y, cp, acc[2*q+1]);
    }
  }
  #pragma unroll
  for (int j = 0; j < 32; ++j){
    float2 t = upk2(acc[j]); acc[j] = pk2(fmaxf(t.x,0.0f), fmaxf(t.y,0.0f));
  }
  #pragma unroll 1
  for (int c = 0; c < 3; ++c){
    const ulonglong2* w = (const ulonglong2*)(cCW3 + c*64);
    u64 a0=0ull, a1=0ull;
    #pragma unroll
    for (int q = 0; q < 16; ++q){
      ulonglong2 wv = w[q];
      a0 = ffma2(wv.x, acc[2*q],   a0);
      a1 = ffma2(wv.y, acc[2*q+1], a1);
    }
    float bias = sm[OFF_CB3+c];
    float2 t0=upk2(a0), t1=upk2(a1);
    rgb[c] = 1.0f / (1.0f + __expf(-(bias + ((t0.x+t1.x)+(t0.y+t1.y)))));
  }
}

__global__ void __launch_bounds__(TPB, 2)
k_points(const float* __restrict__ rays_o, const float* __restrict__ rays_d,
         const float* __restrict__ grid,
         const float* __restrict__ sw1, const float* __restrict__ sb1,
         const float* __restrict__ sb2, const float* __restrict__ sb3,
         const float* __restrict__ cw1, const float* __restrict__ cb1,
         const float* __restrict__ cb2, const float* __restrict__ cb3,
         const float* __restrict__ beta_p,
         const unsigned* __restrict__ near_p, const unsigned* __restrict__ far_p,
         float* __restrict__ out_grads)
{
  extern __shared__ __align__(16) float sm[];
  const int tid = threadIdx.x;

  // ---- cooperative staging of SMALL arrays ----
  for (int i = tid; i < 1024; i += TPB) sm[OFF_W1+i]=sw1[i];
  for (int i = tid; i < 1536; i += TPB) sm[OFF_CW1P+i] = 0.0f;
  if (tid < 64){ sm[OFF_B1+tid]=sb1[tid]; sm[OFF_B2+tid]=sb2[tid];
                 sm[OFF_CB1+tid]=cb1[tid]; sm[OFF_CB2+tid]=cb2[tid]; }
  if (tid < 16) sm[OFF_B3+tid]=sb3[tid];
  if (tid < 3)  sm[OFF_CB3+tid]=cb3[tid];
  __syncthreads();
  for (int i = tid; i < 1152; i += TPB){
    int j = i / 18, c = i - j*18;
    sm[OFF_CW1P + j*24 + c] = cw1[i];
  }
  __syncthreads();

  u64* s1p = ((u64*)(sm + OFF_S1)) + tid;   // per-thread scratch, stride TPB per k

  // warp = one ray; lane l: A = sample l, B = sample l+32
  const int wid  = tid >> 5;
  const int lane = tid & 31;
  const int ray  = blockIdx.x*4 + wid;
  const int pA = ray*64 + lane;
  const int pB = pA + 32;

  const float nearf = decode_scalar(near_p);
  const float farf  = decode_scalar(far_p);
  const float span  = farf - nearf;

  // ---- geometry + forward gather (packed embeddings: 8 pairs per point) ----
  Geo gA, gB;
  u64 epA[8], epB[8];

  #pragma unroll
  for (int pi = 0; pi < PPT; ++pi){
    const int p = pi ? pB : pA;
    const int s = p & 63;
    const float tm = nearf + span * ((s + 0.5f) * (1.0f/64.0f));
    const float px = fmaf(tm, rays_d[3*ray+0], rays_o[3*ray+0]);
    const float py = fmaf(tm, rays_d[3*ray+1], rays_o[3*ray+1]);
    const float pz = fmaf(tm, rays_d[3*ray+2], rays_o[3*ray+2]);

    const float HALF = 0.5f*(float)(GG-1);
    float grx = (px*(1.0f/1.3f) + 1.0f)*HALF;
    float gry = (py*(1.0f/1.3f) + 1.0f)*HALF;
    float grz = (pz*(1.0f/1.3f) + 1.0f)*HALF;
    const float GM1 = (float)(GG-1);
    Geo g;
    g.ax = (grx >= 0.0f) && (grx <= GM1);
    g.ay = (gry >= 0.0f) && (gry <= GM1);
    g.az = (grz >= 0.0f) && (grz <= GM1);
    float gcx = fminf(fmaxf(grx,0.0f), GM1);
    float gcy = fminf(fmaxf(gry,0.0f), GM1);
    float gcz = fminf(fmaxf(grz,0.0f), GM1);
    int ix = min((int)gcx, GG-2);
    int iy = min((int)gcy, GG-2);
    int iz = min((int)gcz, GG-2);
    g.fx = gcx - (float)ix;
    g.fy = gcy - (float)iy;
    g.fz = gcz - (float)iz;
    g.base = ((ix*GG + iy)*GG + iz)*EE;

    u64 ep[8];
    #pragma unroll
    for (int i = 0; i < 8; ++i) ep[i] = 0ull;
    #pragma unroll
    for (int dx = 0; dx < 2; ++dx){
      const float wxv = dx ? g.fx : (1.0f - g.fx);
      #pragma unroll
      for (int dy = 0; dy < 2; ++dy){
        const float wyv = dy ? g.fy : (1.0f - g.fy);
        const ulonglong2* gp = (const ulonglong2*)(grid + g.base + dx*SX + dy*SY);
        const float w0 = wxv*wyv*(1.0f - g.fz);
        const float w1 = wxv*wyv*g.fz;
        const u64 w0p = pk2(w0,w0), w1p = pk2(w1,w1);
        #pragma unroll
        for (int i = 0; i < 4; ++i){
          ulonglong2 a = gp[i];
          ep[2*i]   = ffma2(w0p, a.x, ep[2*i]);
          ep[2*i+1] = ffma2(w0p, a.y, ep[2*i+1]);
        }
        #pragma unroll
        for (int i = 0; i < 4; ++i){
          ulonglong2 b = gp[4+i];
          ep[2*i]   = ffma2(w1p, b.x, ep[2*i]);
          ep[2*i+1] = ffma2(w1p, b.y, ep[2*i+1]);
        }
      }
    }
    if (pi){ gB=g;
      #pragma unroll
      for (int i=0;i<8;++i) epB[i]=ep[i];
    } else { gA=g;
      #pragma unroll
      for (int i=0;i<8;++i) epA[i]=ep[i];
    }
  }

  // warp-uniform color-skip flags: fully-masked halves contribute exactly 0 to 'rendered'
  const bool inA = gA.ax && gA.ay && gA.az;
  const bool inB = gB.ax && gB.ay && gB.az;
  const bool skipA = __all_sync(0xffffffffu, !inA);
  const bool skipB = __all_sync(0xffffffffu, !inB);

  // ---- SDF layers 1+2 fused: h2 accumulators packed (32 pairs per point) ----
  u64 h2A[32], h2B[32];
  #pragma unroll
  for (int j = 0; j < 32; ++j){
    u64 b = ((const u64*)(sm + OFF_B2))[j];
    h2A[j]=b; h2B[j]=b;
  }

  #pragma unroll 2
  for (int k = 0; k < 64; ++k){
    const ulonglong2* w1p = (const ulonglong2*)(sm + OFF_W1 + k*16);
    ulonglong2 wa=w1p[0], wb=w1p[1], wc=w1p[2], wd=w1p[3];
    const float b1 = sm[OFF_B1+k];
    u64 zA0=0ull, zA1=0ull, zB0=0ull, zB1=0ull;
    zA0=ffma2(wa.x,epA[0],zA0); zA1=ffma2(wa.y,epA[1],zA1);
    zA0=ffma2(wb.x,epA[2],zA0); zA1=ffma2(wb.y,epA[3],zA1);
    zA0=ffma2(wc.x,epA[4],zA0); zA1=ffma2(wc.y,epA[5],zA1);
    zA0=ffma2(wd.x,epA[6],zA0); zA1=ffma2(wd.y,epA[7],zA1);
    zB0=ffma2(wa.x,epB[0],zB0); zB1=ffma2(wa.y,epB[1],zB1);
    zB0=ffma2(wb.x,epB[2],zB0); zB1=ffma2(wb.y,epB[3],zB1);
    zB0=ffma2(wc.x,epB[4],zB0); zB1=ffma2(wc.y,epB[5],zB1);
    zB0=ffma2(wd.x,epB[6],zB0); zB1=ffma2(wd.y,epB[7],zB1);
    float2 a0=upk2(zA0), a1=upk2(zA1), b0=upk2(zB0), b1v=upk2(zB1);
    float zA = b1 + ((a0.x+a1.x)+(a0.y+a1.y));
    float zB = b1 + ((b0.x+b1v.x)+(b0.y+b1v.y));
    float hA = softplus100(zA);
    float hB = softplus100(zB);
    // stash sigmoid(100 z1) for the backward pass (per-thread scratch, no sync)
    s1p[k*TPB] = pk2(dact_h(hA), dact_h(hB));
    const u64 hAp = pk2(hA,hA), hBp = pk2(hB,hB);
    const ulonglong2* w2p = (const ulonglong2*)(cW2T + k*64);
    #pragma unroll
    for (int q = 0; q < 16; ++q){
      ulonglong2 wv = w2p[q];
      h2A[2*q]   = ffma2(wv.x, hAp, h2A[2*q]);
      h2A[2*q+1] = ffma2(wv.y, hAp, h2A[2*q+1]);
      h2B[2*q]   = ffma2(wv.x, hBp, h2B[2*q]);
      h2B[2*q+1] = ffma2(wv.y, hBp, h2B[2*q+1]);
    }
  }
  // activation in place
  #pragma unroll
  for (int j = 0; j < 32; ++j){
    float2 ta = upk2(h2A[j]); h2A[j] = pk2(softplus100(ta.x), softplus100(ta.y));
    float2 tb = upk2(h2B[j]); h2B[j] = pk2(softplus100(tb.x), softplus100(tb.y));
  }

  // ---- layer 3: sdf (row 0) always, feat rows only where the color MLP will run ----
  float sdfA, sdfB;
  float featA[15], featB[15];
  {
    const ulonglong2* w = (const ulonglong2*)(cW3);
    u64 aA0=0ull,aA1=0ull,aB0=0ull,aB1=0ull;
    #pragma unroll
    for (int q = 0; q < 16; ++q){
      ulonglong2 wv = w[q];
      aA0 = ffma2(wv.x, h2A[2*q],   aA0);
      aA1 = ffma2(wv.y, h2A[2*q+1], aA1);
      aB0 = ffma2(wv.x, h2B[2*q],   aB0);
      aB1 = ffma2(wv.y, h2B[2*q+1], aB1);
    }
    float bias = sm[OFF_B3];
    float2 ta0=upk2(aA0), ta1=upk2(aA1), tb0=upk2(aB0), tb1=upk2(aB1);
    sdfA = bias + ((ta0.x+ta1.x)+(ta0.y+ta1.y));
    sdfB = bias + ((tb0.x+tb1.x)+(tb0.y+tb1.y));
  }
  if (!skipA && !skipB){
    #pragma unroll 1
    for (int c = 1; c < 16; ++c){
      const ulonglong2* w = (const ulonglong2*)(cW3 + c*64);
      u64 aA0=0ull,aA1=0ull,aB0=0ull,aB1=0ull;
      #pragma unroll
      for (int q = 0; q < 16; ++q){
        ulonglong2 wv = w[q];
        aA0 = ffma2(wv.x, h2A[2*q],   aA0);
        aA1 = ffma2(wv.y, h2A[2*q+1], aA1);
        aB0 = ffma2(wv.x, h2B[2*q],   aB0);
        aB1 = ffma2(wv.y, h2B[2*q+1], aB1);
      }
      float bias = sm[OFF_B3+c];
      float2 ta0=upk2(aA0), ta1=upk2(aA1), tb0=upk2(aB0), tb1=upk2(aB1);
      featA[c-1] = bias + ((ta0.x+ta1.x)+(ta0.y+ta1.y));
      featB[c-1] = bias + ((tb0.x+tb1.x)+(tb0.y+tb1.y));
    }
  } else if (!skipA || !skipB){
    const u64* h2 = skipB ? h2A : h2B;
    float* feat   = skipB ? featA : featB;
    #pragma unroll 1
    for (int c = 1; c < 16; ++c){
      const ulonglong2* w = (const ulonglong2*)(cW3 + c*64);
      u64 a0=0ull, a1=0ull;
      #pragma unroll
      for (int q = 0; q < 16; ++q){
        ulonglong2 wv = w[q];
        a0 = ffma2(wv.x, h2[2*q],   a0);
        a1 = ffma2(wv.y, h2[2*q+1], a1);
      }
      float bias = sm[OFF_B3+c];
      float2 t0=upk2(a0), t1=upk2(a1);
      feat[c-1] = bias + ((t0.x+t1.x)+(t0.y+t1.y));
    }
  }

  // ---- backward: g2 = W3[0][:] * sigmoid(100 z2), overwrite h2 (packed) ----
  #pragma unroll
  for (int j = 0; j < 32; ++j){
    u64 w3p = ((const u64*)cW3)[j];
    float2 ta = upk2(h2A[j]);
    float2 tb = upk2(h2B[j]);
    h2A[j] = fmul2(w3p, pk2(dact_h(ta.x), dact_h(ta.y)));
    h2B[j] = fmul2(w3p, pk2(dact_h(tb.x), dact_h(tb.y)));
  }

  u64 deA[8], deB[8];
  #pragma unroll
  for (int i = 0; i < 8; ++i){ deA[i]=0ull; deB[i]=0ull; }

  #pragma unroll 2
  for (int k = 0; k < 64; ++k){
    const ulonglong2* w2p = (const ulonglong2*)(cW2T + k*64);
    u64 aA0=0ull,aA1=0ull,aB0=0ull,aB1=0ull;
    #pragma unroll
    for (int q = 0; q < 16; ++q){
      ulonglong2 wv = w2p[q];
      aA0 = ffma2(wv.x, h2A[2*q],   aA0);
      aA1 = ffma2(wv.y, h2A[2*q+1], aA1);
      aB0 = ffma2(wv.x, h2B[2*q],   aB0);
      aB1 = ffma2(wv.y, h2B[2*q+1], aB1);
    }
    float2 ta0=upk2(aA0), ta1=upk2(aA1), tb0=upk2(aB0), tb1=upk2(aB1);
    float sumA = (ta0.x+ta1.x)+(ta0.y+ta1.y);
    float sumB = (tb0.x+tb1.x)+(tb0.y+tb1.y);

    // load stored sigmoid(100 z1) instead of recomputing the preactivation
    float2 sv = upk2(s1p[k*TPB]);
    const float dzA = sumA * sv.x;
    const float dzB = sumB * sv.y;

    const ulonglong2* w1p = (const ulonglong2*)(sm + OFF_W1 + k*16);
    ulonglong2 wa=w1p[0], wb=w1p[1], wc=w1p[2], wd=w1p[3];
    const u64 dzAp = pk2(dzA,dzA), dzBp = pk2(dzB,dzB);
    deA[0]=ffma2(dzAp,wa.x,deA[0]); deA[1]=ffma2(dzAp,wa.y,deA[1]);
    deA[2]=ffma2(dzAp,wb.x,deA[2]); deA[3]=ffma2(dzAp,wb.y,deA[3]);
    deA[4]=ffma2(dzAp,wc.x,deA[4]); deA[5]=ffma2(dzAp,wc.y,deA[5]);
    deA[6]=ffma2(dzAp,wd.x,deA[6]); deA[7]=ffma2(dzAp,wd.y,deA[7]);
    deB[0]=ffma2(dzBp,wa.x,deB[0]); deB[1]=ffma2(dzBp,wa.y,deB[1]);
    deB[2]=ffma2(dzBp,wb.x,deB[2]); deB[3]=ffma2(dzBp,wb.y,deB[3]);
    deB[4]=ffma2(dzBp,wc.x,deB[4]); deB[5]=ffma2(dzBp,wc.y,deB[5]);
    deB[6]=ffma2(dzBp,wd.x,deB[6]); deB[7]=ffma2(dzBp,wd.y,deB[7]);
  }

  // ---- re-gather corners (packed dot) -> spatial gradient; normals ----
  float nxA,nyA,nzA, nxB,nyB,nzB;
  #pragma unroll
  for (int pi = 0; pi < PPT; ++pi){
    const Geo g = pi ? gB : gA;
    const u64* de = pi ? deB : deA;
    float gx=0.f, gy=0.f, gz=0.f;
    #pragma unroll
    for (int dx = 0; dx < 2; ++dx){
      const float wxv = dx ? g.fx : (1.0f - g.fx);
      #pragma unroll
      for (int dy = 0; dy < 2; ++dy){
        const float wyv = dy ? g.fy : (1.0f - g.fy);
        const ulonglong2* gp = (const ulonglong2*)(grid + g.base + dx*SX + dy*SY);
        u64 acc0=0ull, acc1=0ull;
        #pragma unroll
        for (int i = 0; i < 4; ++i){
          ulonglong2 a = gp[i];
          acc0 = ffma2(a.x, de[2*i],   acc0);
          acc0 = ffma2(a.y, de[2*i+1], acc0);
        }
        #pragma unroll
        for (int i = 0; i < 4; ++i){
          ulonglong2 b = gp[4+i];
          acc1 = ffma2(b.x, de[2*i],   acc1);
          acc1 = ffma2(b.y, de[2*i+1], acc1);
        }
        float2 t0 = upk2(acc0), t1 = upk2(acc1);
        float sA = t0.x + t0.y;
        float sB = t1.x + t1.y;
        float sc = fmaf(g.fz, sB - sA, sA);
        gz = fmaf(wxv*wyv, sB - sA, gz);
        gx += dx ? wyv*sc : -wyv*sc;
        gy += dy ? wxv*sc : -wxv*sc;
      }
    }
    const float SCALE = 0.5f*(float)(GG-1)/1.3f;
    const float Gx = g.ax ? gx*SCALE : 0.0f;
    const float Gy = g.ay ? gy*SCALE : 0.0f;
    const float Gz = g.az ? gz*SCALE : 0.0f;
    const int p = pi ? pB : pA;
    out_grads[3*p+0] = Gx;
    out_grads[3*p+1] = Gy;
    out_grads[3*p+2] = Gz;
    const float nn = sqrtf(Gx*Gx + Gy*Gy + Gz*Gz);
    const float inv = 1.0f / fmaxf(nn, 1e-12f);
    if (pi){ nxB=Gx*inv; nyB=Gy*inv; nzB=Gz*inv; }
    else   { nxA=Gx*inv; nyA=Gy*inv; nzA=Gz*inv; }
  }

  // ---- color MLP: skip fully-masked halves (their w is exactly 0 in compositing) ----
  float rgbA[3] = {0.f,0.f,0.f}, rgbB[3] = {0.f,0.f,0.f};

  if (!skipA && !skipB){
    u64 ciA[9], ciB[9];
    #pragma unroll
    for (int i = 0; i < 7; ++i){
      ciA[i] = pk2(featA[2*i], featA[2*i+1]);
      ciB[i] = pk2(featB[2*i], featB[2*i+1]);
    }
    ciA[7] = pk2(featA[14], nxA); ciA[8] = pk2(nyA, nzA);
    ciB[7] = pk2(featB[14], nxB); ciB[8] = pk2(nyB, nzB);

    #pragma unroll
    for (int j = 0; j < 32; ++j){
      u64 b = ((const u64*)(sm + OFF_CB2))[j];
      h2A[j]=b; h2B[j]=b;
    }

    #pragma unroll 1
    for (int j = 0; j < 64; ++j){
      const ulonglong2* w = (const ulonglong2*)(sm + OFF_CW1P + j*24);
      ulonglong2 wa=w[0], wb=w[1], wc=w[2], wd=w[3];
      u64 w8 = ((const u64*)(sm + OFF_CW1P + j*24))[8];
      const float bias = sm[OFF_CB1+j];
      u64 zA0=0ull, zA1=0ull, zB0=0ull, zB1=0ull;
      zA0=ffma2(wa.x,ciA[0],zA0); zA1=ffma2(wa.y,ciA[1],zA1);
      zA0=ffma2(wb.x,ciA[2],zA0); zA1=ffma2(wb.y,ciA[3],zA1);
      zA0=ffma2(wc.x,ciA[4],zA0); zA1=ffma2(wc.y,ciA[5],zA1);
      zA0=ffma2(wd.x,ciA[6],zA0); zA1=ffma2(wd.y,ciA[7],zA1);
      zA0=ffma2(w8,  ciA[8],zA0);
      zB0=ffma2(wa.x,ciB[0],zB0); zB1=ffma2(wa.y,ciB[1],zB1);
      zB0=ffma2(wb.x,ciB[2],zB0); zB1=ffma2(wb.y,ciB[3],zB1);
      zB0=ffma2(wc.x,ciB[4],zB0); zB1=ffma2(wc.y,ciB[5],zB1);
      zB0=ffma2(wd.x,ciB[6],zB0); zB1=ffma2(wd.y,ciB[7],zB1);
      zB0=ffma2(w8,  ciB[8],zB0);
      float2 ta0=upk2(zA0), ta1=upk2(zA1), tb0=upk2(zB0), tb1=upk2(zB1);
      float zA = bias + ((ta0.x+ta1.x)+(ta0.y+ta1.y));
      float zB = bias + ((tb0.x+tb1.x)+(tb0.y+tb1.y));
      float c1A = fmaxf(zA, 0.0f);
      float c1B = fmaxf(zB, 0.0f);
      const u64 cAp = pk2(c1A,c1A), cBp = pk2(c1B,c1B);
      const ulonglong2* wt = (const ulonglong2*)(cCW2T + j*64);
      #pragma unroll
      for (int q = 0; q < 16; ++q){
        ulonglong2 wv = wt[q];
        h2A[2*q]   = ffma2(wv.x, cAp, h2A[2*q]);
        h2A[2*q+1] = ffma2(wv.y, cAp, h2A[2*q+1]);
        h2B[2*q]   = ffma2(wv.x, cBp, h2B[2*q]);
        h2B[2*q+1] = ffma2(wv.y, cBp, h2B[2*q+1]);
      }
    }
    #pragma unroll
    for (int j = 0; j < 32; ++j){
      float2 ta = upk2(h2A[j]); h2A[j] = pk2(fmaxf(ta.x,0.0f), fmaxf(ta.y,0.0f));
      float2 tb = upk2(h2B[j]); h2B[j] = pk2(fmaxf(tb.x,0.0f), fmaxf(tb.y,0.0f));
    }

    #pragma unroll 1
    for (int c = 0; c < 3; ++c){
      const ulonglong2* w = (const ulonglong2*)(cCW3 + c*64);
      u64 aA0=0ull,aA1=0ull,aB0=0ull,aB1=0ull;
      #pragma unroll
      for (int q = 0; q < 16; ++q){
        ulonglong2 wv = w[q];
        aA0 = ffma2(wv.x, h2A[2*q],   aA0);
        aA1 = ffma2(wv.y, h2A[2*q+1], aA1);
        aB0 = ffma2(wv.x, h2B[2*q],   aB0);
        aB1 = ffma2(wv.y, h2B[2*q+1], aB1);
      }
      float bias = sm[OFF_CB3+c];
      float2 ta0=upk2(aA0), ta1=upk2(aA1), tb0=upk2(aB0), tb1=upk2(aB1);
      rgbA[c] = 1.0f / (1.0f + __expf(-(bias + ((ta0.x+ta1.x)+(ta0.y+ta1.y)))));
      rgbB[c] = 1.0f / (1.0f + __expf(-(bias + ((tb0.x+tb1.x)+(tb0.y+tb1.y)))));
    }
  } else if (!skipA || !skipB){
    // one half fully masked -> single-point color path for the live half
    u64 ci[9];
    const float* feat = skipB ? featA : featB;
    const float nx = skipB ? nxA : nxB;
    const float ny = skipB ? nyA : nyB;
    const float nz = skipB ? nzA : nzB;
    #pragma unroll
    for (int i = 0; i < 7; ++i) ci[i] = pk2(feat[2*i], feat[2*i+1]);
    ci[7] = pk2(feat[14], nx); ci[8] = pk2(ny, nz);
    float rgb[3];
    color_single(sm, ci, h2A, rgb);
    if (skipB){ rgbA[0]=rgb[0]; rgbA[1]=rgb[1]; rgbA[2]=rgb[2]; }
    else      { rgbB[0]=rgb[0]; rgbB[1]=rgb[1]; rgbB[2]=rgb[2]; }
  }
  // both skipped: rgb stays 0 (multiplied by exactly-zero weights downstream)

  // ---- sigma (Laplace CDF) + stores ----
  const float bet = 0.015f + fabsf(beta_p[0]);
  {
    const float s = sdfA;
    const float sgn = (s > 0.0f) ? 1.0f : ((s < 0.0f) ? -1.0f : 0.0f);
    float sigma = (0.5f + 0.5f*sgn*expm1f(-fabsf(s)/bet)) / bet;
    if (!inA) sigma = 0.0f;
    g_srgb[pA] = make_float4(sigma, rgbA[0], rgbA[1], rgbA[2]);
    g_nrm[pA]  = make_float4(nxA, nyA, nzA, 0.0f);
  }
  {
    const float s = sdfB;
    const float sgn = (s > 0.0f) ? 1.0f : ((s < 0.0f) ? -1.0f : 0.0f);
    float sigma = (0.5f + 0.5f*sgn*expm1f(-fabsf(s)/bet)) / bet;
    if (!inB) sigma = 0.0f;
    g_srgb[pB] = make_float4(sigma, rgbB[0], rgbB[1], rgbB[2]);
    g_nrm[pB]  = make_float4(nxB, nyB, nzB, 0.0f);
  }
}

// ---- per-ray compositing: one warp per ray, 2 samples per lane ----
__global__ void __launch_bounds__(256)
k_render(const float* __restrict__ rdn,
         const unsigned* __restrict__ near_p, const unsigned* __restrict__ far_p,
         float* __restrict__ out)
{
  const int gt = blockIdx.x*256 + threadIdx.x;
  const int r = gt >> 5;
  const int lane = gt & 31;
  if (r >= RR) return;

  const float nearf = decode_scalar(near_p);
  const float farf  = decode_scalar(far_p);
  const float span  = farf - nearf;
  const float dt    = span * (1.0f/64.0f);

  const int p0 = r*64 + lane, p1 = p0 + 32;
  float4 a0 = g_srgb[p0], a1 = g_srgb[p1];
  float4 n0 = g_nrm[p0],  n1 = g_nrm[p1];
  const float dd0 = a0.x * dt;
  const float dd1 = a1.x * dt;

  float cs0 = dd0;
  #pragma unroll
  for (int o = 1; o < 32; o <<= 1){ float v = __shfl_up_sync(0xffffffffu, cs0, o); if (lane >= o) cs0 += v; }
  const float tot0 = __shfl_sync(0xffffffffu, cs0, 31);
  float cs1 = dd1;
  #pragma unroll
  for (int o = 1; o < 32; o <<= 1){ float v = __shfl_up_sync(0xffffffffu, cs1, o); if (lane >= o) cs1 += v; }
  cs1 += tot0;

  const float T0 = __expf(dd0 - cs0);
  const float T1 = __expf(dd1 - cs1);
  const float w0 = (1.0f - __expf(-dd0)) * T0;
  const float w1 = (1.0f - __expf(-dd1)) * T1;
  const float tm0 = nearf + span * (((float)lane + 0.5f)  * (1.0f/64.0f));
  const float tm1 = nearf + span * (((float)lane + 32.5f) * (1.0f/64.0f));

  float v0 = w0*a0.y + w1*a1.y;
  float v1 = w0*a0.z + w1*a1.z;
  float v2 = w0*a0.w + w1*a1.w;
  float v3 = w0*tm0  + w1*tm1;
  float v4 = w0*n0.x + w1*n1.x;
  float v5 = w0*n0.y + w1*n1.y;
  float v6 = w0*n0.z + w1*n1.z;
  float v7 = w0 + w1;

  #pragma unroll
  for (int o = 16; o > 0; o >>= 1){
    v0 += __shfl_down_sync(0xffffffffu, v0, o);
    v1 += __shfl_down_sync(0xffffffffu, v1, o);
    v2 += __shfl_down_sync(0xffffffffu, v2, o);
    v3 += __shfl_down_sync(0xffffffffu, v3, o);
    v4 += __shfl_down_sync(0xffffffffu, v4, o);
    v5 += __shfl_down_sync(0xffffffffu, v5, o);
    v6 += __shfl_down_sync(0xffffffffu, v6, o);
    v7 += __shfl_down_sync(0xffffffffu, v7, o);
  }
  if (lane == 0){
    float* op = out + r*8;
    op[0]=v0; op[1]=v1; op[2]=v2;
    op[3]=v3 / rdn[r];
    op[4]=v4; op[5]=v5; op[6]=v6; op[7]=v7;
  }
}

extern "C" void kernel_launch(void* const* d_in, const int* in_sizes, int n_in,
                              void* d_out, int out_size)
{
  const float* rays_o = (const float*)d_in[0];
  const float* rays_d = (const float*)d_in[1];
  const float* rdn    = (const float*)d_in[2];
  const float* grid   = (const float*)d_in[3];
  const float* sw1 = (const float*)d_in[4];
  const float* sb1 = (const float*)d_in[5];
  const float* sw2 = (const float*)d_in[6];
  const float* sb2 = (const float*)d_in[7];
  const float* sw3 = (const float*)d_in[8];
  const float* sb3 = (const float*)d_in[9];
  const float* cw1 = (const float*)d_in[10];
  const float* cb1 = (const float*)d_in[11];
  const float* cw2 = (const float*)d_in[12];
  const float* cb2 = (const float*)d_in[13];
  const float* cw3 = (const float*)d_in[14];
  const float* cb3 = (const float*)d_in[15];
  const float* beta = (const float*)d_in[16];
  const unsigned* nearp = (const unsigned*)d_in[17];
  const unsigned* farp  = (const unsigned*)d_in[18];

  float* out = (float*)d_out;
  float* out_grads = out + RR*8;   // output = [rendered (R,8), sdf_grads (R*S,3)]

  // Resolve constant-bank addresses (pure address queries; no stream work).
  void *w2t_p = nullptr, *cw2t_p = nullptr, *w3_p = nullptr, *cw3_p = nullptr;
  cudaGetSymbolAddress(&w2t_p,  cW2T);
  cudaGetSymbolAddress(&cw2t_p, cCW2T);
  cudaGetSymbolAddress(&w3_p,   cW3);
  cudaGetSymbolAddress(&cw3_p,  cCW3);

  cudaFuncSetAttribute(k_points, cudaFuncAttributeMaxDynamicSharedMemorySize, SMEM_BYTES);

  // 1) prep kernel writes transposed weights straight into the constant bank
  k_prep<<<1, 256>>>(sw2, cw2, sw3, cw3,
                     (float*)w2t_p, (float*)cw2t_p, (float*)w3_p, (float*)cw3_p);

  // 2) main point kernel + compositing
  k_points<<<RR/4, TPB, SMEM_BYTES>>>(
      rays_o, rays_d, grid,
      sw1, sb1, sb2, sb3,
      cw1, cb1, cb2, cb3,
      beta, nearp, farp, out_grads);

  k_render<<<(RR*32)/256, 256>>>(rdn, nearp, farp, out);
}